// round 3
// baseline (speedup 1.0000x reference)
#include <cuda_runtime.h>
#include <cuda_bf16.h>
#include <math.h>
#include <stdint.h>

// ---------------------------------------------------------------------------
// QBNN attention.
// B=2, S=2048, E=1024, H=16, hd=64.
//
// Pipeline:
//  1) gemm_bias_tc: Q,K,V projections + output projection on tensor pipe
//     (mma.sync bf16 with hi/lo split compensation, fp32-grade accuracy)
//  2) prep:   Qcat=[Q/8, lam*tanh(Q)@J_h], Kcat=[K, tanh(K)], Vh head-major
//  3) flash:  causal attention, dk=128, dv=64, online softmax (fp32 CUDA cores)
// ---------------------------------------------------------------------------

#define N_TOK   4096        // B*S
#define EMB     1024
#define HEADS   16
#define HD      64
#define SEQ     2048
#define BH      32          // B*HEADS

// scratch arena (floats)
#define OFF_Q   0
#define OFF_K   (OFF_Q  + N_TOK*EMB)
#define OFF_V   (OFF_K  + N_TOK*EMB)
#define OFF_QC  (OFF_V  + N_TOK*EMB)          // [BH][SEQ][128]
#define OFF_KC  (OFF_QC + BH*SEQ*128)         // [BH][SEQ][128]
#define OFF_VH  (OFF_KC + BH*SEQ*128)         // [BH][SEQ][64]
#define OFF_O   (OFF_VH + BH*SEQ*64)          // [N_TOK][EMB]
#define SCRATCH_FLOATS (OFF_O + N_TOK*EMB)

__device__ float g_scratch[SCRATCH_FLOATS];

// ---------------------------------------------------------------------------
// Tensor-core GEMM: C[M x 1024] = A[M x 1024] @ W[1024 x 1024] + bias
// mma.sync.m16n8k16 bf16, hi/lo split compensation (3 MMAs): err ~3e-5.
// CTA tile 128x128, 8 warps, warp tile 64x32, BK=32.
// smem row stride 40 bf16 -> conflict-free fragment loads.
// ---------------------------------------------------------------------------
#define MMA16816(d, a0, a1, a2, a3, b0, b1)                                  \
    asm volatile(                                                            \
        "mma.sync.aligned.m16n8k16.row.col.f32.bf16.bf16.f32 "               \
        "{%0,%1,%2,%3}, {%4,%5,%6,%7}, {%8,%9}, {%0,%1,%2,%3};"              \
        : "+f"(d[0]), "+f"(d[1]), "+f"(d[2]), "+f"(d[3])                     \
        : "r"(a0), "r"(a1), "r"(a2), "r"(a3), "r"(b0), "r"(b1))

#define SMS 40   // smem row stride in bf16 elements

__global__ __launch_bounds__(256, 1)
void gemm_bias_tc(const float* __restrict__ A, const float* __restrict__ W,
                  const float* __restrict__ bias, float* __restrict__ C, int M)
{
    const int K = 1024, N = 1024;
    __shared__ __nv_bfloat16 Ah[128 * SMS];
    __shared__ __nv_bfloat16 Al[128 * SMS];
    __shared__ __nv_bfloat16 Bh[128 * SMS];   // stored transposed: [n][k]
    __shared__ __nv_bfloat16 Bl[128 * SMS];

    int tid  = threadIdx.x;
    int warp = tid >> 5;
    int lane = tid & 31;
    int wm   = warp & 1;        // 2 m-groups of 64
    int wn   = warp >> 1;       // 4 n-groups of 32
    int g    = lane >> 2;       // 0..7
    int tq   = lane & 3;        // 0..3
    int m0   = blockIdx.y * 128;
    int n0   = blockIdx.x * 128;

    float acc[4][4][4];
#pragma unroll
    for (int mi = 0; mi < 4; mi++)
#pragma unroll
        for (int nj = 0; nj < 4; nj++)
#pragma unroll
            for (int t = 0; t < 4; t++) acc[mi][nj][t] = 0.f;

    for (int k0 = 0; k0 < K; k0 += 32) {
        __syncthreads();
        // load A tile [128 x 32] fp32, split to hi/lo bf16
#pragma unroll
        for (int it = 0; it < 4; it++) {
            int idx = tid + it * 256;
            int r   = idx >> 3;
            int c4  = (idx & 7) << 2;
            float4 v = *(const float4*)&A[(size_t)(m0 + r) * K + k0 + c4];
            float va[4] = {v.x, v.y, v.z, v.w};
#pragma unroll
            for (int i = 0; i < 4; i++) {
                __nv_bfloat16 h = __float2bfloat16_rn(va[i]);
                __nv_bfloat16 l = __float2bfloat16_rn(va[i] - __bfloat162float(h));
                Ah[r * SMS + c4 + i] = h;
                Al[r * SMS + c4 + i] = l;
            }
        }
        // load B tile [32 x 128] fp32, transpose + split into Bs[n][k]
#pragma unroll
        for (int it = 0; it < 4; it++) {
            int idx = tid + it * 256;
            int r   = idx >> 5;            // k-row 0..31
            int c4  = (idx & 31) << 2;     // n col
            float4 v = *(const float4*)&W[(size_t)(k0 + r) * N + n0 + c4];
            float va[4] = {v.x, v.y, v.z, v.w};
#pragma unroll
            for (int i = 0; i < 4; i++) {
                __nv_bfloat16 h = __float2bfloat16_rn(va[i]);
                __nv_bfloat16 l = __float2bfloat16_rn(va[i] - __bfloat162float(h));
                Bh[(c4 + i) * SMS + r] = h;
                Bl[(c4 + i) * SMS + r] = l;
            }
        }
        __syncthreads();

#pragma unroll
        for (int kk = 0; kk < 32; kk += 16) {
            uint32_t afh[4][4], afl[4][4], bfh[4][2], bfl[4][2];
#pragma unroll
            for (int mi = 0; mi < 4; mi++) {
                int r0 = (wm * 64 + mi * 16 + g) * SMS;
                int r1 = r0 + 8 * SMS;
                int c  = kk + tq * 2;
                afh[mi][0] = *(const uint32_t*)&Ah[r0 + c];
                afh[mi][1] = *(const uint32_t*)&Ah[r1 + c];
                afh[mi][2] = *(const uint32_t*)&Ah[r0 + c + 8];
                afh[mi][3] = *(const uint32_t*)&Ah[r1 + c + 8];
                afl[mi][0] = *(const uint32_t*)&Al[r0 + c];
                afl[mi][1] = *(const uint32_t*)&Al[r1 + c];
                afl[mi][2] = *(const uint32_t*)&Al[r0 + c + 8];
                afl[mi][3] = *(const uint32_t*)&Al[r1 + c + 8];
            }
#pragma unroll
            for (int nj = 0; nj < 4; nj++) {
                int cc = (wn * 32 + nj * 8 + g) * SMS;
                int kc = kk + tq * 2;
                bfh[nj][0] = *(const uint32_t*)&Bh[cc + kc];
                bfh[nj][1] = *(const uint32_t*)&Bh[cc + kc + 8];
                bfl[nj][0] = *(const uint32_t*)&Bl[cc + kc];
                bfl[nj][1] = *(const uint32_t*)&Bl[cc + kc + 8];
            }
#pragma unroll
            for (int mi = 0; mi < 4; mi++)
#pragma unroll
                for (int nj = 0; nj < 4; nj++) {
                    MMA16816(acc[mi][nj], afh[mi][0], afh[mi][1], afh[mi][2], afh[mi][3],
                             bfh[nj][0], bfh[nj][1]);
                    MMA16816(acc[mi][nj], afh[mi][0], afh[mi][1], afh[mi][2], afh[mi][3],
                             bfl[nj][0], bfl[nj][1]);
                    MMA16816(acc[mi][nj], afl[mi][0], afl[mi][1], afl[mi][2], afl[mi][3],
                             bfh[nj][0], bfh[nj][1]);
                }
        }
    }

    // epilogue: bias + store
#pragma unroll
    for (int mi = 0; mi < 4; mi++) {
        size_t r0 = (size_t)(m0 + wm * 64 + mi * 16 + g);
        size_t r1 = r0 + 8;
#pragma unroll
        for (int nj = 0; nj < 4; nj++) {
            int c = n0 + wn * 32 + nj * 8 + tq * 2;
            float b0 = bias[c], b1 = bias[c + 1];
            float2 w0 = make_float2(acc[mi][nj][0] + b0, acc[mi][nj][1] + b1);
            float2 w1 = make_float2(acc[mi][nj][2] + b0, acc[mi][nj][3] + b1);
            *(float2*)&C[r0 * N + c] = w0;
            *(float2*)&C[r1 * N + c] = w1;
        }
    }
}

// ---------------------------------------------------------------------------
// prep: build Qcat, Kcat, Vh (head-major). Block: (64 dims x 8 tokens), one head.
// ---------------------------------------------------------------------------
__global__ __launch_bounds__(512)
void prep_kernel(const float* __restrict__ Qb, const float* __restrict__ Kb,
                 const float* __restrict__ Vb, const float* __restrict__ J,
                 const float* __restrict__ lamp,
                 float* __restrict__ Qcat, float* __restrict__ Kcat,
                 float* __restrict__ Vh)
{
    __shared__ float Js[4096];       // J[h] 64x64
    __shared__ float qn[8][64];

    int h   = blockIdx.y;
    int d   = threadIdx.x;           // 0..63
    int ty  = threadIdx.y;           // 0..7
    int tid = ty * 64 + d;

    for (int i = tid; i < 4096; i += 512) Js[i] = J[h * 4096 + i];

    int tok = blockIdx.x * 8 + ty;
    int b   = tok >> 11;
    int s   = tok & 2047;
    int bh  = (b << 4) + h;

    float q = Qb[(size_t)tok * EMB + h * HD + d];
    float k = Kb[(size_t)tok * EMB + h * HD + d];
    float v = Vb[(size_t)tok * EMB + h * HD + d];
    qn[ty][d] = tanhf(q);
    __syncthreads();

    float accv = 0.f;
#pragma unroll 8
    for (int dd = 0; dd < 64; dd++) accv += qn[ty][dd] * Js[dd * 64 + d];

    float lam = lamp[0];
    size_t base = (size_t)bh * SEQ + s;
    Qcat[base * 128 + d]      = q * 0.125f;      // 1/sqrt(64)
    Qcat[base * 128 + 64 + d] = lam * accv;
    Kcat[base * 128 + d]      = k;
    Kcat[base * 128 + 64 + d] = tanhf(k);
    Vh  [base * 64  + d]      = v;
}

// ---------------------------------------------------------------------------
// flash: causal attention, dk=128, dv=64. Tile 64q x 64k, 256 threads,
// 4x4 micro-tile per thread (16x16 thread grid).
// ---------------------------------------------------------------------------
#define FL_SMEM_FLOATS (128*68 + 128*68 + 64*64 + 64*68)
#define FL_SMEM_BYTES  (FL_SMEM_FLOATS * 4)

__global__ __launch_bounds__(256, 1)
void flash_kernel(const float* __restrict__ Qcat, const float* __restrict__ Kcat,
                  const float* __restrict__ Vh, float* __restrict__ O)
{
    extern __shared__ float sm[];
    float* Qst = sm;                       // [d][r] stride 68
    float* Kst = Qst + 128 * 68;           // [d][j] stride 68
    float* Vs  = Kst + 128 * 68;           // [j][c] stride 64
    float* Pst = Vs  + 64 * 64;            // [j][r] stride 68

    int bh  = blockIdx.y;
    int qt  = gridDim.x - 1 - blockIdx.x;  // heavy tiles scheduled first
    int tid = threadIdx.x;
    int tr  = tid >> 4;                    // 0..15 -> rows tr*4..+3
    int tc  = tid & 15;                    // 0..15 -> cols tc*4..+3

    const float* Qg = Qcat + ((size_t)bh * SEQ + qt * 64) * 128;
    for (int idx = tid; idx < 2048; idx += 256) {      // 64 rows * 32 float4
        int r  = idx >> 5;
        int d4 = (idx & 31) << 2;
        float4 v = *(const float4*)&Qg[r * 128 + d4];
        Qst[(d4 + 0) * 68 + r] = v.x;
        Qst[(d4 + 1) * 68 + r] = v.y;
        Qst[(d4 + 2) * 68 + r] = v.z;
        Qst[(d4 + 3) * 68 + r] = v.w;
    }

    float acc[4][4];
#pragma unroll
    for (int i = 0; i < 4; i++)
#pragma unroll
        for (int j = 0; j < 4; j++) acc[i][j] = 0.f;
    float mrow[4] = {-1e30f, -1e30f, -1e30f, -1e30f};
    float lrow[4] = {0.f, 0.f, 0.f, 0.f};

    for (int kt = 0; kt <= qt; kt++) {
        __syncthreads();   // protect Kst/Vs/Pst from previous iteration readers
        const float* Kg = Kcat + ((size_t)bh * SEQ + kt * 64) * 128;
        const float* Vg = Vh   + ((size_t)bh * SEQ + kt * 64) * 64;
        for (int idx = tid; idx < 2048; idx += 256) {
            int r  = idx >> 5;
            int d4 = (idx & 31) << 2;
            float4 v = *(const float4*)&Kg[r * 128 + d4];
            Kst[(d4 + 0) * 68 + r] = v.x;
            Kst[(d4 + 1) * 68 + r] = v.y;
            Kst[(d4 + 2) * 68 + r] = v.z;
            Kst[(d4 + 3) * 68 + r] = v.w;
        }
        for (int idx = tid; idx < 1024; idx += 256) {  // 64 rows * 16 float4
            int j  = idx >> 4;
            int c4 = (idx & 15) << 2;
            *(float4*)&Vs[j * 64 + c4] = *(const float4*)&Vg[j * 64 + c4];
        }
        __syncthreads();

        float s[4][4];
#pragma unroll
        for (int i = 0; i < 4; i++)
#pragma unroll
            for (int j = 0; j < 4; j++) s[i][j] = 0.f;

#pragma unroll 4
        for (int d = 0; d < 128; d++) {
            float4 qv = *(const float4*)&Qst[d * 68 + tr * 4];
            float4 kv = *(const float4*)&Kst[d * 68 + tc * 4];
            float q0 = qv.x, q1 = qv.y, q2 = qv.z, q3 = qv.w;
            float k0 = kv.x, k1 = kv.y, k2 = kv.z, k3 = kv.w;
            s[0][0] += q0 * k0; s[0][1] += q0 * k1; s[0][2] += q0 * k2; s[0][3] += q0 * k3;
            s[1][0] += q1 * k0; s[1][1] += q1 * k1; s[1][2] += q1 * k2; s[1][3] += q1 * k3;
            s[2][0] += q2 * k0; s[2][1] += q2 * k1; s[2][2] += q2 * k2; s[2][3] += q2 * k3;
            s[3][0] += q3 * k0; s[3][1] += q3 * k1; s[3][2] += q3 * k2; s[3][3] += q3 * k3;
        }

        if (kt == qt) {   // diagonal tile: apply causal mask
#pragma unroll
            for (int ri = 0; ri < 4; ri++) {
                int ig = tr * 4 + ri;
#pragma unroll
                for (int jc = 0; jc < 4; jc++) {
                    if (tc * 4 + jc > ig) s[ri][jc] = -1e30f;
                }
            }
        }

        // online softmax update (row group = 16 lanes sharing tr)
#pragma unroll
        for (int ri = 0; ri < 4; ri++) {
            float tm = fmaxf(fmaxf(s[ri][0], s[ri][1]), fmaxf(s[ri][2], s[ri][3]));
            tm = fmaxf(tm, __shfl_xor_sync(0xffffffffu, tm, 1));
            tm = fmaxf(tm, __shfl_xor_sync(0xffffffffu, tm, 2));
            tm = fmaxf(tm, __shfl_xor_sync(0xffffffffu, tm, 4));
            tm = fmaxf(tm, __shfl_xor_sync(0xffffffffu, tm, 8));
            float mnew = fmaxf(mrow[ri], tm);
            float corr = __expf(mrow[ri] - mnew);
            mrow[ri] = mnew;
            float ps = 0.f;
#pragma unroll
            for (int jc = 0; jc < 4; jc++) {
                float p = __expf(s[ri][jc] - mnew);
                s[ri][jc] = p;
                ps += p;
            }
            ps += __shfl_xor_sync(0xffffffffu, ps, 1);
            ps += __shfl_xor_sync(0xffffffffu, ps, 2);
            ps += __shfl_xor_sync(0xffffffffu, ps, 4);
            ps += __shfl_xor_sync(0xffffffffu, ps, 8);
            lrow[ri] = lrow[ri] * corr + ps;
#pragma unroll
            for (int cc = 0; cc < 4; cc++) acc[ri][cc] *= corr;
        }

        // write P transposed: Pst[j][r]
#pragma unroll
        for (int jc = 0; jc < 4; jc++) {
            float4 w = make_float4(s[0][jc], s[1][jc], s[2][jc], s[3][jc]);
            *(float4*)&Pst[(tc * 4 + jc) * 68 + tr * 4] = w;
        }
        __syncthreads();

        // O += P @ V
#pragma unroll 4
        for (int j = 0; j < 64; j++) {
            float4 pv = *(const float4*)&Pst[j * 68 + tr * 4];
            float4 vv = *(const float4*)&Vs [j * 64 + tc * 4];
            float p0 = pv.x, p1 = pv.y, p2 = pv.z, p3 = pv.w;
            float v0 = vv.x, v1 = vv.y, v2 = vv.z, v3 = vv.w;
            acc[0][0] += p0 * v0; acc[0][1] += p0 * v1; acc[0][2] += p0 * v2; acc[0][3] += p0 * v3;
            acc[1][0] += p1 * v0; acc[1][1] += p1 * v1; acc[1][2] += p1 * v2; acc[1][3] += p1 * v3;
            acc[2][0] += p2 * v0; acc[2][1] += p2 * v1; acc[2][2] += p2 * v2; acc[2][3] += p2 * v3;
            acc[3][0] += p3 * v0; acc[3][1] += p3 * v1; acc[3][2] += p3 * v2; acc[3][3] += p3 * v3;
        }
    }

    // epilogue: normalize + write to token-major O (B,S,E)
    int b = bh >> 4;
    int h = bh & 15;
    float* Og = O + ((size_t)(b * SEQ + qt * 64)) * EMB + h * HD;
#pragma unroll
    for (int ri = 0; ri < 4; ri++) {
        float inv = 1.0f / lrow[ri];
        float4 o = make_float4(acc[ri][0] * inv, acc[ri][1] * inv,
                               acc[ri][2] * inv, acc[ri][3] * inv);
        *(float4*)&Og[(size_t)(tr * 4 + ri) * EMB + tc * 4] = o;
    }
}

// ---------------------------------------------------------------------------
// launch
// ---------------------------------------------------------------------------
extern "C" void kernel_launch(void* const* d_in, const int* in_sizes, int n_in,
                              void* d_out, int out_size)
{
    const float* x   = (const float*)d_in[0];
    const float* Wq  = (const float*)d_in[1];
    const float* bq  = (const float*)d_in[2];
    const float* Wk  = (const float*)d_in[3];
    const float* bk  = (const float*)d_in[4];
    const float* Wv  = (const float*)d_in[5];
    const float* bv  = (const float*)d_in[6];
    const float* Wo  = (const float*)d_in[7];
    const float* bo  = (const float*)d_in[8];
    const float* J   = (const float*)d_in[9];
    const float* lam = (const float*)d_in[10];
    float* out = (float*)d_out;

    void* scratch_v = nullptr;
    cudaGetSymbolAddress(&scratch_v, g_scratch);
    float* scr  = (float*)scratch_v;
    float* gQ   = scr + OFF_Q;
    float* gK   = scr + OFF_K;
    float* gV   = scr + OFF_V;
    float* gQC  = scr + OFF_QC;
    float* gKC  = scr + OFF_KC;
    float* gVH  = scr + OFF_VH;
    float* gO   = scr + OFF_O;

    dim3 gemm_grid(8, N_TOK / 128);
    dim3 gemm_blk(256);

    gemm_bias_tc<<<gemm_grid, gemm_blk>>>(x, Wq, bq, gQ, N_TOK);
    gemm_bias_tc<<<gemm_grid, gemm_blk>>>(x, Wk, bk, gK, N_TOK);
    gemm_bias_tc<<<gemm_grid, gemm_blk>>>(x, Wv, bv, gV, N_TOK);

    dim3 prep_grid(N_TOK / 8, HEADS);
    dim3 prep_blk(64, 8);
    prep_kernel<<<prep_grid, prep_blk>>>(gQ, gK, gV, J, lam, gQC, gKC, gVH);

    cudaFuncSetAttribute(flash_kernel, cudaFuncAttributeMaxDynamicSharedMemorySize,
                         FL_SMEM_BYTES);
    dim3 fl_grid(SEQ / 64, BH);
    flash_kernel<<<fl_grid, 256, FL_SMEM_BYTES>>>(gQC, gKC, gVH, gO);

    gemm_bias_tc<<<gemm_grid, gemm_blk>>>(gO, Wo, bo, out, N_TOK);
}

// round 5
// speedup vs baseline: 1.3141x; 1.3141x over previous
#include <cuda_runtime.h>
#include <cuda_bf16.h>
#include <math.h>
#include <stdint.h>

// ---------------------------------------------------------------------------
// QBNN attention. B=2, S=2048, E=1024, H=16, hd=64.
//
//  0) split kernels: x -> (xh,xl) bf16 ; W* -> transposed (h,l) bf16
//  1) gemm_bf16c: C = A@W + b via 3-pass compensated bf16 mma
//     (AhWh + AhWl + AlWh), cp.async double-buffered
//  2) prep:   Qcat=[Q/8, lam*tanh(Q)@J_h], Kcat=[K, tanh(K)], Vh head-major
//  3) flash:  causal attention, dk=128, dv=64 (fp32 CUDA cores)
//  4) split gO, gemm_bf16c -> out
// ---------------------------------------------------------------------------

#define N_TOK   4096
#define EMB     1024
#define HEADS   16
#define HD      64
#define SEQ     2048
#define BH      32

// fp32 scratch
#define OFF_Q   0
#define OFF_K   (OFF_Q  + N_TOK*EMB)
#define OFF_V   (OFF_K  + N_TOK*EMB)
#define OFF_QC  (OFF_V  + N_TOK*EMB)
#define OFF_KC  (OFF_QC + BH*SEQ*128)
#define OFF_VH  (OFF_KC + BH*SEQ*128)
#define OFF_O   (OFF_VH + BH*SEQ*64)
#define SCRATCH_FLOATS (OFF_O + N_TOK*EMB)
__device__ float g_scratch[SCRATCH_FLOATS];

// bf16 scratch
#define BOFF_XH   0
#define BOFF_XL   (BOFF_XH + N_TOK*EMB)
#define BOFF_W    (BOFF_XL + N_TOK*EMB)          // 4 weights * (h,l) * 1M
#define BOFF_OH   (BOFF_W  + 8*EMB*EMB)
#define BOFF_OL   (BOFF_OH + N_TOK*EMB)
#define BSCRATCH  (BOFF_OL + N_TOK*EMB)
__device__ __nv_bfloat16 g_bscratch[BSCRATCH];

// ---------------------------------------------------------------------------
// split: fp32 -> hi/lo bf16 (elementwise)
// ---------------------------------------------------------------------------
__global__ __launch_bounds__(256)
void split_kernel(const float* __restrict__ src, __nv_bfloat16* __restrict__ h,
                  __nv_bfloat16* __restrict__ l, int n4)
{
    int i = blockIdx.x * blockDim.x + threadIdx.x;
    if (i >= n4) return;
    float4 v = ((const float4*)src)[i];
    float va[4] = {v.x, v.y, v.z, v.w};
    __nv_bfloat16 hh[4], ll[4];
#pragma unroll
    for (int j = 0; j < 4; j++) {
        hh[j] = __float2bfloat16_rn(va[j]);
        ll[j] = __float2bfloat16_rn(va[j] - __bfloat162float(hh[j]));
    }
    ((uint2*)h)[i] = *(uint2*)hh;
    ((uint2*)l)[i] = *(uint2*)ll;
}

// ---------------------------------------------------------------------------
// split+transpose: W[k][n] fp32 -> Wt{h,l}[n][k] bf16. 32x32 tiles.
// ---------------------------------------------------------------------------
__global__ __launch_bounds__(256)
void split_transpose_kernel(const float* __restrict__ W,
                            __nv_bfloat16* __restrict__ th,
                            __nv_bfloat16* __restrict__ tl)
{
    __shared__ float tile[32][33];
    int k0 = blockIdx.y * 32;
    int n0 = blockIdx.x * 32;
    int tx = threadIdx.x & 31;
    int ty = threadIdx.x >> 5;     // 0..7
#pragma unroll
    for (int j = 0; j < 4; j++)
        tile[ty + j * 8][tx] = W[(size_t)(k0 + ty + j * 8) * EMB + n0 + tx];
    __syncthreads();
#pragma unroll
    for (int j = 0; j < 4; j++) {
        int n = ty + j * 8;
        float v = tile[tx][n];
        __nv_bfloat16 h = __float2bfloat16_rn(v);
        __nv_bfloat16 l = __float2bfloat16_rn(v - __bfloat162float(h));
        th[(size_t)(n0 + n) * EMB + k0 + tx] = h;
        tl[(size_t)(n0 + n) * EMB + k0 + tx] = l;
    }
}

// ---------------------------------------------------------------------------
// Compensated bf16 tensor-core GEMM.
// C[4096 x 1024] = A[4096 x 1024] @ W[1024 x 1024] + bias
// A given as (Ah, Al) row-major [m][k]; W as transposed (Bh, Bl) [n][k].
// 3 passes: AhBh + AhBl + AlBh. CTA 128x128, 8 warps (2x4), warp 64x32,
// BK=32, cp.async 2-stage pipeline, smem stride 40 (conflict-free).
// ---------------------------------------------------------------------------
#define SMS   40
#define STG   (128 * SMS)

#define MMA16816(d, a0, a1, a2, a3, b0, b1)                                  \
    asm volatile(                                                            \
        "mma.sync.aligned.m16n8k16.row.col.f32.bf16.bf16.f32 "               \
        "{%0,%1,%2,%3}, {%4,%5,%6,%7}, {%8,%9}, {%0,%1,%2,%3};"              \
        : "+f"(d[0]), "+f"(d[1]), "+f"(d[2]), "+f"(d[3])                     \
        : "r"(a0), "r"(a1), "r"(a2), "r"(a3), "r"(b0), "r"(b1))

__device__ __forceinline__ void cp_async16(void* smem_dst, const void* gmem_src)
{
    uint32_t s = (uint32_t)__cvta_generic_to_shared(smem_dst);
    asm volatile("cp.async.cg.shared.global [%0], [%1], 16;\n" :: "r"(s), "l"(gmem_src));
}

__global__ __launch_bounds__(256, 2)
void gemm_bf16c(const __nv_bfloat16* __restrict__ Ah,
                const __nv_bfloat16* __restrict__ Al,
                const __nv_bfloat16* __restrict__ Bh,
                const __nv_bfloat16* __restrict__ Bl,
                const float* __restrict__ bias, float* __restrict__ C)
{
    const int K = 1024, N = 1024;
    __shared__ __nv_bfloat16 sA[2 * STG];
    __shared__ __nv_bfloat16 sB[2 * STG];

    int tid  = threadIdx.x;
    int warp = tid >> 5;
    int lane = tid & 31;
    int wm   = warp & 1;
    int wn   = warp >> 1;
    int g    = lane >> 2;
    int tq   = lane & 3;
    int m0   = blockIdx.y * 128;
    int n0   = blockIdx.x * 128;

    const __nv_bfloat16* passA[3] = {Ah, Ah, Al};
    const __nv_bfloat16* passB[3] = {Bh, Bl, Bh};

    float acc[4][4][4];
#pragma unroll
    for (int mi = 0; mi < 4; mi++)
#pragma unroll
        for (int nj = 0; nj < 4; nj++)
#pragma unroll
            for (int t = 0; t < 4; t++) acc[mi][nj][t] = 0.f;

    // tile loader: 128 rows x 32 cols bf16 = 8192 B = 512 16B-chunks per operand
    auto issue = [&](int t, int s) {
        int p  = t >> 5;
        int k0 = (t & 31) << 5;
        const __nv_bfloat16* Ap = passA[p] + (size_t)m0 * K + k0;
        const __nv_bfloat16* Bp = passB[p] + (size_t)n0 * K + k0;
        __nv_bfloat16* sa = sA + s * STG;
        __nv_bfloat16* sb = sB + s * STG;
#pragma unroll
        for (int i = 0; i < 2; i++) {
            int chunk = i * 256 + tid;          // 0..511
            int r = chunk >> 2;                 // 0..127
            int c = (chunk & 3) << 3;           // 0,8,16,24
            cp_async16(&sa[r * SMS + c], Ap + (size_t)r * K + c);
            cp_async16(&sb[r * SMS + c], Bp + (size_t)r * K + c);
        }
        asm volatile("cp.async.commit_group;\n");
    };

    issue(0, 0);

    for (int t = 0; t < 96; t++) {
        int s = t & 1;
        if (t + 1 < 96) {
            issue(t + 1, s ^ 1);
            asm volatile("cp.async.wait_group 1;\n");
        } else {
            asm volatile("cp.async.wait_group 0;\n");
        }
        __syncthreads();

        const __nv_bfloat16* sa = sA + s * STG;
        const __nv_bfloat16* sb = sB + s * STG;
#pragma unroll
        for (int kk = 0; kk < 32; kk += 16) {
            uint32_t af[4][4], bf_[4][2];
#pragma unroll
            for (int mi = 0; mi < 4; mi++) {
                int r0 = (wm * 64 + mi * 16 + g) * SMS;
                int c  = kk + tq * 2;
                af[mi][0] = *(const uint32_t*)&sa[r0 + c];
                af[mi][1] = *(const uint32_t*)&sa[r0 + 8 * SMS + c];
                af[mi][2] = *(const uint32_t*)&sa[r0 + c + 8];
                af[mi][3] = *(const uint32_t*)&sa[r0 + 8 * SMS + c + 8];
            }
#pragma unroll
            for (int nj = 0; nj < 4; nj++) {
                int cc = (wn * 32 + nj * 8 + g) * SMS + kk + tq * 2;
                bf_[nj][0] = *(const uint32_t*)&sb[cc];
                bf_[nj][1] = *(const uint32_t*)&sb[cc + 8];
            }
#pragma unroll
            for (int mi = 0; mi < 4; mi++)
#pragma unroll
                for (int nj = 0; nj < 4; nj++)
                    MMA16816(acc[mi][nj], af[mi][0], af[mi][1], af[mi][2], af[mi][3],
                             bf_[nj][0], bf_[nj][1]);
        }
        __syncthreads();
    }

    // epilogue: bias + store
#pragma unroll
    for (int mi = 0; mi < 4; mi++) {
        size_t r0 = (size_t)(m0 + wm * 64 + mi * 16 + g);
        size_t r1 = r0 + 8;
#pragma unroll
        for (int nj = 0; nj < 4; nj++) {
            int c = n0 + wn * 32 + nj * 8 + tq * 2;
            float b0 = bias[c], b1 = bias[c + 1];
            float2 w0 = make_float2(acc[mi][nj][0] + b0, acc[mi][nj][1] + b1);
            float2 w1 = make_float2(acc[mi][nj][2] + b0, acc[mi][nj][3] + b1);
            *(float2*)&C[r0 * N + c] = w0;
            *(float2*)&C[r1 * N + c] = w1;
        }
    }
}

// ---------------------------------------------------------------------------
// prep: build Qcat, Kcat, Vh (head-major).
// ---------------------------------------------------------------------------
__global__ __launch_bounds__(512)
void prep_kernel(const float* __restrict__ Qb, const float* __restrict__ Kb,
                 const float* __restrict__ Vb, const float* __restrict__ J,
                 const float* __restrict__ lamp,
                 float* __restrict__ Qcat, float* __restrict__ Kcat,
                 float* __restrict__ Vh)
{
    __shared__ float Js[4096];
    __shared__ float qn[8][64];

    int h   = blockIdx.y;
    int d   = threadIdx.x;
    int ty  = threadIdx.y;
    int tid = ty * 64 + d;

    for (int i = tid; i < 4096; i += 512) Js[i] = J[h * 4096 + i];

    int tok = blockIdx.x * 8 + ty;
    int b   = tok >> 11;
    int s   = tok & 2047;
    int bh  = (b << 4) + h;

    float q = Qb[(size_t)tok * EMB + h * HD + d];
    float k = Kb[(size_t)tok * EMB + h * HD + d];
    float v = Vb[(size_t)tok * EMB + h * HD + d];
    qn[ty][d] = tanhf(q);
    __syncthreads();

    float accv = 0.f;
#pragma unroll 8
    for (int dd = 0; dd < 64; dd++) accv += qn[ty][dd] * Js[dd * 64 + d];

    float lam = lamp[0];
    size_t base = (size_t)bh * SEQ + s;
    Qcat[base * 128 + d]      = q * 0.125f;
    Qcat[base * 128 + 64 + d] = lam * accv;
    Kcat[base * 128 + d]      = k;
    Kcat[base * 128 + 64 + d] = tanhf(k);
    Vh  [base * 64  + d]      = v;
}

// ---------------------------------------------------------------------------
// flash: causal attention, dk=128, dv=64 (fp32 CUDA cores).
// ---------------------------------------------------------------------------
#define FL_SMEM_FLOATS (128*68 + 128*68 + 64*64 + 64*68)
#define FL_SMEM_BYTES  (FL_SMEM_FLOATS * 4)

__global__ __launch_bounds__(256, 1)
void flash_kernel(const float* __restrict__ Qcat, const float* __restrict__ Kcat,
                  const float* __restrict__ Vh, float* __restrict__ O)
{
    extern __shared__ float sm[];
    float* Qst = sm;
    float* Kst = Qst + 128 * 68;
    float* Vs  = Kst + 128 * 68;
    float* Pst = Vs  + 64 * 64;

    int bh  = blockIdx.y;
    int qt  = gridDim.x - 1 - blockIdx.x;
    int tid = threadIdx.x;
    int tr  = tid >> 4;
    int tc  = tid & 15;

    const float* Qg = Qcat + ((size_t)bh * SEQ + qt * 64) * 128;
    for (int idx = tid; idx < 2048; idx += 256) {
        int r  = idx >> 5;
        int d4 = (idx & 31) << 2;
        float4 v = *(const float4*)&Qg[r * 128 + d4];
        Qst[(d4 + 0) * 68 + r] = v.x;
        Qst[(d4 + 1) * 68 + r] = v.y;
        Qst[(d4 + 2) * 68 + r] = v.z;
        Qst[(d4 + 3) * 68 + r] = v.w;
    }

    float acc[4][4];
#pragma unroll
    for (int i = 0; i < 4; i++)
#pragma unroll
        for (int j = 0; j < 4; j++) acc[i][j] = 0.f;
    float mrow[4] = {-1e30f, -1e30f, -1e30f, -1e30f};
    float lrow[4] = {0.f, 0.f, 0.f, 0.f};

    for (int kt = 0; kt <= qt; kt++) {
        __syncthreads();
        const float* Kg = Kcat + ((size_t)bh * SEQ + kt * 64) * 128;
        const float* Vg = Vh   + ((size_t)bh * SEQ + kt * 64) * 64;
        for (int idx = tid; idx < 2048; idx += 256) {
            int r  = idx >> 5;
            int d4 = (idx & 31) << 2;
            float4 v = *(const float4*)&Kg[r * 128 + d4];
            Kst[(d4 + 0) * 68 + r] = v.x;
            Kst[(d4 + 1) * 68 + r] = v.y;
            Kst[(d4 + 2) * 68 + r] = v.z;
            Kst[(d4 + 3) * 68 + r] = v.w;
        }
        for (int idx = tid; idx < 1024; idx += 256) {
            int j  = idx >> 4;
            int c4 = (idx & 15) << 2;
            *(float4*)&Vs[j * 64 + c4] = *(const float4*)&Vg[j * 64 + c4];
        }
        __syncthreads();

        float s[4][4];
#pragma unroll
        for (int i = 0; i < 4; i++)
#pragma unroll
            for (int j = 0; j < 4; j++) s[i][j] = 0.f;

#pragma unroll 4
        for (int d = 0; d < 128; d++) {
            float4 qv = *(const float4*)&Qst[d * 68 + tr * 4];
            float4 kv = *(const float4*)&Kst[d * 68 + tc * 4];
            float q0 = qv.x, q1 = qv.y, q2 = qv.z, q3 = qv.w;
            float k0 = kv.x, k1 = kv.y, k2 = kv.z, k3 = kv.w;
            s[0][0] += q0 * k0; s[0][1] += q0 * k1; s[0][2] += q0 * k2; s[0][3] += q0 * k3;
            s[1][0] += q1 * k0; s[1][1] += q1 * k1; s[1][2] += q1 * k2; s[1][3] += q1 * k3;
            s[2][0] += q2 * k0; s[2][1] += q2 * k1; s[2][2] += q2 * k2; s[2][3] += q2 * k3;
            s[3][0] += q3 * k0; s[3][1] += q3 * k1; s[3][2] += q3 * k2; s[3][3] += q3 * k3;
        }

        if (kt == qt) {
#pragma unroll
            for (int ri = 0; ri < 4; ri++) {
                int ig = tr * 4 + ri;
#pragma unroll
                for (int jc = 0; jc < 4; jc++) {
                    if (tc * 4 + jc > ig) s[ri][jc] = -1e30f;
                }
            }
        }

#pragma unroll
        for (int ri = 0; ri < 4; ri++) {
            float tm = fmaxf(fmaxf(s[ri][0], s[ri][1]), fmaxf(s[ri][2], s[ri][3]));
            tm = fmaxf(tm, __shfl_xor_sync(0xffffffffu, tm, 1));
            tm = fmaxf(tm, __shfl_xor_sync(0xffffffffu, tm, 2));
            tm = fmaxf(tm, __shfl_xor_sync(0xffffffffu, tm, 4));
            tm = fmaxf(tm, __shfl_xor_sync(0xffffffffu, tm, 8));
            float mnew = fmaxf(mrow[ri], tm);
            float corr = __expf(mrow[ri] - mnew);
            mrow[ri] = mnew;
            float ps = 0.f;
#pragma unroll
            for (int jc = 0; jc < 4; jc++) {
                float p = __expf(s[ri][jc] - mnew);
                s[ri][jc] = p;
                ps += p;
            }
            ps += __shfl_xor_sync(0xffffffffu, ps, 1);
            ps += __shfl_xor_sync(0xffffffffu, ps, 2);
            ps += __shfl_xor_sync(0xffffffffu, ps, 4);
            ps += __shfl_xor_sync(0xffffffffu, ps, 8);
            lrow[ri] = lrow[ri] * corr + ps;
#pragma unroll
            for (int cc = 0; cc < 4; cc++) acc[ri][cc] *= corr;
        }

#pragma unroll
        for (int jc = 0; jc < 4; jc++) {
            float4 w = make_float4(s[0][jc], s[1][jc], s[2][jc], s[3][jc]);
            *(float4*)&Pst[(tc * 4 + jc) * 68 + tr * 4] = w;
        }
        __syncthreads();

#pragma unroll 4
        for (int j = 0; j < 64; j++) {
            float4 pv = *(const float4*)&Pst[j * 68 + tr * 4];
            float4 vv = *(const float4*)&Vs [j * 64 + tc * 4];
            float p0 = pv.x, p1 = pv.y, p2 = pv.z, p3 = pv.w;
            float v0 = vv.x, v1 = vv.y, v2 = vv.z, v3 = vv.w;
            acc[0][0] += p0 * v0; acc[0][1] += p0 * v1; acc[0][2] += p0 * v2; acc[0][3] += p0 * v3;
            acc[1][0] += p1 * v0; acc[1][1] += p1 * v1; acc[1][2] += p1 * v2; acc[1][3] += p1 * v3;
            acc[2][0] += p2 * v0; acc[2][1] += p2 * v1; acc[2][2] += p2 * v2; acc[2][3] += p2 * v3;
            acc[3][0] += p3 * v0; acc[3][1] += p3 * v1; acc[3][2] += p3 * v2; acc[3][3] += p3 * v3;
        }
    }

    int b = bh >> 4;
    int h = bh & 15;
    float* Og = O + ((size_t)(b * SEQ + qt * 64)) * EMB + h * HD;
#pragma unroll
    for (int ri = 0; ri < 4; ri++) {
        float inv = 1.0f / lrow[ri];
        float4 o = make_float4(acc[ri][0] * inv, acc[ri][1] * inv,
                               acc[ri][2] * inv, acc[ri][3] * inv);
        *(float4*)&Og[(size_t)(tr * 4 + ri) * EMB + tc * 4] = o;
    }
}

// ---------------------------------------------------------------------------
// launch
// ---------------------------------------------------------------------------
extern "C" void kernel_launch(void* const* d_in, const int* in_sizes, int n_in,
                              void* d_out, int out_size)
{
    const float* x   = (const float*)d_in[0];
    const float* Wq  = (const float*)d_in[1];
    const float* bq  = (const float*)d_in[2];
    const float* Wk  = (const float*)d_in[3];
    const float* bk  = (const float*)d_in[4];
    const float* Wv  = (const float*)d_in[5];
    const float* bv  = (const float*)d_in[6];
    const float* Wo  = (const float*)d_in[7];
    const float* bo  = (const float*)d_in[8];
    const float* J   = (const float*)d_in[9];
    const float* lam = (const float*)d_in[10];
    float* out = (float*)d_out;

    void* p = nullptr;
    cudaGetSymbolAddress(&p, g_scratch);
    float* scr = (float*)p;
    float* gQ  = scr + OFF_Q;
    float* gK  = scr + OFF_K;
    float* gV  = scr + OFF_V;
    float* gQC = scr + OFF_QC;
    float* gKC = scr + OFF_KC;
    float* gVH = scr + OFF_VH;
    float* gO  = scr + OFF_O;

    cudaGetSymbolAddress(&p, g_bscratch);
    __nv_bfloat16* bscr = (__nv_bfloat16*)p;
    __nv_bfloat16* xh = bscr + BOFF_XH;
    __nv_bfloat16* xl = bscr + BOFF_XL;
    __nv_bfloat16* wt = bscr + BOFF_W;      // [4 weights][h|l][1M]
    __nv_bfloat16* oh = bscr + BOFF_OH;
    __nv_bfloat16* ol = bscr + BOFF_OL;

    const int WSZ = EMB * EMB;
    __nv_bfloat16* wqh = wt + 0 * WSZ; __nv_bfloat16* wql = wt + 1 * WSZ;
    __nv_bfloat16* wkh = wt + 2 * WSZ; __nv_bfloat16* wkl = wt + 3 * WSZ;
    __nv_bfloat16* wvh = wt + 4 * WSZ; __nv_bfloat16* wvl = wt + 5 * WSZ;
    __nv_bfloat16* woh = wt + 6 * WSZ; __nv_bfloat16* wol = wt + 7 * WSZ;

    // conversions
    split_kernel<<<(N_TOK * EMB / 4 + 255) / 256, 256>>>(x, xh, xl, N_TOK * EMB / 4);
    dim3 tg(32, 32), tb(256);
    split_transpose_kernel<<<tg, tb>>>(Wq, wqh, wql);
    split_transpose_kernel<<<tg, tb>>>(Wk, wkh, wkl);
    split_transpose_kernel<<<tg, tb>>>(Wv, wvh, wvl);
    split_transpose_kernel<<<tg, tb>>>(Wo, woh, wol);

    dim3 gg(8, 32), gb(256);
    gemm_bf16c<<<gg, gb>>>(xh, xl, wqh, wql, bq, gQ);
    gemm_bf16c<<<gg, gb>>>(xh, xl, wkh, wkl, bk, gK);
    gemm_bf16c<<<gg, gb>>>(xh, xl, wvh, wvl, bv, gV);

    dim3 prep_grid(N_TOK / 8, HEADS), prep_blk(64, 8);
    prep_kernel<<<prep_grid, prep_blk>>>(gQ, gK, gV, J, lam, gQC, gKC, gVH);

    cudaFuncSetAttribute(flash_kernel, cudaFuncAttributeMaxDynamicSharedMemorySize,
                         FL_SMEM_BYTES);
    dim3 fl_grid(SEQ / 64, BH);
    flash_kernel<<<fl_grid, 256, FL_SMEM_BYTES>>>(gQC, gKC, gVH, gO);

    split_kernel<<<(N_TOK * EMB / 4 + 255) / 256, 256>>>(gO, oh, ol, N_TOK * EMB / 4);
    gemm_bf16c<<<gg, gb>>>(oh, ol, woh, wol, bo, out);
}

// round 7
// speedup vs baseline: 1.4560x; 1.1080x over previous
#include <cuda_runtime.h>
#include <cuda_bf16.h>
#include <math.h>
#include <stdint.h>

// ---------------------------------------------------------------------------
// QBNN attention. B=2, S=2048, E=1024, H=16, hd=64.
//
//  0) split kernels: x -> (xh,xl) bf16 ; W* -> transposed (h,l) bf16
//  1) gemm_bf16c: C = A@W + b, 3-pass compensated bf16 mma.sync
//     (AhWh + AhWl + AlWh), ldmatrix + SW128 swizzle, 3-stage cp.async
//  2) prep:   Qcat=[Q/8, lam*tanh(Q)@J_h], Kcat=[K, tanh(K)], Vh head-major
//  3) flash:  causal attention, dk=128, dv=64 (fp32 CUDA cores)
//  4) split gO, gemm_bf16c -> out
// ---------------------------------------------------------------------------

#define N_TOK   4096
#define EMB     1024
#define HEADS   16
#define HD      64
#define SEQ     2048
#define BH      32

// fp32 scratch
#define OFF_Q   0
#define OFF_K   (OFF_Q  + N_TOK*EMB)
#define OFF_V   (OFF_K  + N_TOK*EMB)
#define OFF_QC  (OFF_V  + N_TOK*EMB)
#define OFF_KC  (OFF_QC + BH*SEQ*128)
#define OFF_VH  (OFF_KC + BH*SEQ*128)
#define OFF_O   (OFF_VH + BH*SEQ*64)
#define SCRATCH_FLOATS (OFF_O + N_TOK*EMB)
__device__ float g_scratch[SCRATCH_FLOATS];

// bf16 scratch
#define BOFF_XH   0
#define BOFF_XL   (BOFF_XH + N_TOK*EMB)
#define BOFF_W    (BOFF_XL + N_TOK*EMB)
#define BOFF_OH   (BOFF_W  + 8*EMB*EMB)
#define BOFF_OL   (BOFF_OH + N_TOK*EMB)
#define BSCRATCH  (BOFF_OL + N_TOK*EMB)
__device__ __nv_bfloat16 g_bscratch[BSCRATCH];

// ---------------------------------------------------------------------------
// split: fp32 -> hi/lo bf16
// ---------------------------------------------------------------------------
__global__ __launch_bounds__(256)
void split_kernel(const float* __restrict__ src, __nv_bfloat16* __restrict__ h,
                  __nv_bfloat16* __restrict__ l, int n4)
{
    int i = blockIdx.x * blockDim.x + threadIdx.x;
    if (i >= n4) return;
    float4 v = ((const float4*)src)[i];
    float va[4] = {v.x, v.y, v.z, v.w};
    __nv_bfloat16 hh[4], ll[4];
#pragma unroll
    for (int j = 0; j < 4; j++) {
        hh[j] = __float2bfloat16_rn(va[j]);
        ll[j] = __float2bfloat16_rn(va[j] - __bfloat162float(hh[j]));
    }
    ((uint2*)h)[i] = *(uint2*)hh;
    ((uint2*)l)[i] = *(uint2*)ll;
}

// ---------------------------------------------------------------------------
// split+transpose: W[k][n] fp32 -> Wt{h,l}[n][k] bf16
// ---------------------------------------------------------------------------
__global__ __launch_bounds__(256)
void split_transpose_kernel(const float* __restrict__ W,
                            __nv_bfloat16* __restrict__ th,
                            __nv_bfloat16* __restrict__ tl)
{
    __shared__ float tile[32][33];
    int k0 = blockIdx.y * 32;
    int n0 = blockIdx.x * 32;
    int tx = threadIdx.x & 31;
    int ty = threadIdx.x >> 5;
#pragma unroll
    for (int j = 0; j < 4; j++)
        tile[ty + j * 8][tx] = W[(size_t)(k0 + ty + j * 8) * EMB + n0 + tx];
    __syncthreads();
#pragma unroll
    for (int j = 0; j < 4; j++) {
        int n = ty + j * 8;
        float v = tile[tx][n];
        __nv_bfloat16 h = __float2bfloat16_rn(v);
        __nv_bfloat16 l = __float2bfloat16_rn(v - __bfloat162float(h));
        th[(size_t)(n0 + n) * EMB + k0 + tx] = h;
        tl[(size_t)(n0 + n) * EMB + k0 + tx] = l;
    }
}

// ---------------------------------------------------------------------------
// GEMM helpers
// ---------------------------------------------------------------------------
#define MMA16816(d, a0, a1, a2, a3, b0, b1)                                  \
    asm volatile(                                                            \
        "mma.sync.aligned.m16n8k16.row.col.f32.bf16.bf16.f32 "               \
        "{%0,%1,%2,%3}, {%4,%5,%6,%7}, {%8,%9}, {%0,%1,%2,%3};"              \
        : "+f"(d[0]), "+f"(d[1]), "+f"(d[2]), "+f"(d[3])                     \
        : "r"(a0), "r"(a1), "r"(a2), "r"(a3), "r"(b0), "r"(b1))

#define LDSM_X4(r0, r1, r2, r3, addr)                                        \
    asm volatile("ldmatrix.sync.aligned.m8n8.x4.shared.b16 {%0,%1,%2,%3}, [%4];" \
        : "=r"(r0), "=r"(r1), "=r"(r2), "=r"(r3) : "r"(addr))

__device__ __forceinline__ void cp16s(uint32_t smem_dst, const void* gmem_src)
{
    asm volatile("cp.async.cg.shared.global [%0], [%1], 16;"
                 :: "r"(smem_dst), "l"(gmem_src));
}

// ---------------------------------------------------------------------------
// Compensated bf16 tensor-core GEMM v2.
// C[4096x1024] = A@W + bias. A=(Ah,Al) [m][k]; W=(Bh,Bl) transposed [n][k].
// 3 passes (AhBh + AhBl + AlBh) = 48 chunks of BK=64.
// CTA 128x128, 8 warps (2 wm x 4 wn), warp 64x32.
// smem: SW128 swizzled 128B rows, 3-stage cp.async, 1 sync/tile, ldmatrix.x4.
// ---------------------------------------------------------------------------
#define GSTAGE  32768                // A tile 16KB + B tile 16KB
#define GSMEM   (3 * GSTAGE)         // 96KB

__global__ __launch_bounds__(256, 2)
void gemm_bf16c(const __nv_bfloat16* __restrict__ Ah, const __nv_bfloat16* __restrict__ Al,
                const __nv_bfloat16* __restrict__ Bh, const __nv_bfloat16* __restrict__ Bl,
                const float* __restrict__ bias, float* __restrict__ C)
{
    extern __shared__ __align__(1024) char smem[];
    const int K = 1024, N = 1024;
    uint32_t sbase;
    asm("{ .reg .u64 t; cvta.to.shared.u64 t, %1; cvt.u32.u64 %0, t; }"
        : "=r"(sbase) : "l"(smem));

    int tid  = threadIdx.x;
    int warp = tid >> 5;
    int lane = tid & 31;
    int wm   = warp & 1;
    int wn   = warp >> 1;
    int m0   = blockIdx.y * 128;
    int n0   = blockIdx.x * 128;

    const __nv_bfloat16* pA[3] = {Ah, Ah, Al};
    const __nv_bfloat16* pB[3] = {Bh, Bl, Bh};

    float acc[4][4][4];
#pragma unroll
    for (int mi = 0; mi < 4; mi++)
#pragma unroll
        for (int nj = 0; nj < 4; nj++)
#pragma unroll
            for (int t = 0; t < 4; t++) acc[mi][nj][t] = 0.f;

    // issue one chunk: A 128x64 bf16 (16KB) + B 128x64 (16KB), SW128 swizzle.
    auto issue = [&](int chunk, int stg) {
        int p  = chunk >> 4;
        int k0 = (chunk & 15) << 6;
        const __nv_bfloat16* Ap = pA[p] + (size_t)m0 * K + k0;
        const __nv_bfloat16* Bp = pB[p] + (size_t)n0 * K + k0;
        uint32_t aBuf = sbase + stg * GSTAGE;
        uint32_t bBuf = aBuf + 16384;
#pragma unroll
        for (int i = 0; i < 4; i++) {
            int idx = tid + i * 256;            // 0..1023
            int r   = idx >> 3;                 // row 0..127
            int c   = idx & 7;                  // 16B chunk 0..7
            uint32_t sw = (uint32_t)(r << 7) | ((uint32_t)(c ^ (r & 7)) << 4);
            cp16s(aBuf + sw, Ap + (size_t)r * K + c * 8);
            cp16s(bBuf + sw, Bp + (size_t)r * K + c * 8);
        }
        asm volatile("cp.async.commit_group;");
    };

    issue(0, 0);
    issue(1, 1);

    // ldmatrix lane address helpers
    int lm  = lane >> 3;    // matrix idx 0..3
    int lr  = lane & 7;     // row within matrix

    for (int t = 0; t < 48; t++) {
        int stg = t % 3;
        if (t < 47) asm volatile("cp.async.wait_group 1;");
        else        asm volatile("cp.async.wait_group 0;");
        __syncthreads();

        uint32_t aBuf = sbase + stg * GSTAGE;
        uint32_t bBuf = aBuf + 16384;

#pragma unroll
        for (int kk = 0; kk < 64; kk += 16) {
            int kc = kk >> 3;   // 16B chunk index of kk
            // A fragments: mi=0..3, matrices (m0:r0-7,kc)(m1:r8-15,kc)(m2:r0-7,kc+1)(m3:r8-15,kc+1)
            uint32_t af[4][4];
#pragma unroll
            for (int mi = 0; mi < 4; mi++) {
                int row = wm * 64 + mi * 16 + (lm & 1) * 8 + lr;
                int ch  = kc + (lm >> 1);
                uint32_t ad = aBuf + (uint32_t)(row << 7) + ((uint32_t)(ch ^ (row & 7)) << 4);
                LDSM_X4(af[mi][0], af[mi][1], af[mi][2], af[mi][3], ad);
            }
            // B fragments: nj pairs. matrices (m0:nj,kc)(m1:nj,kc+1)(m2:nj+1,kc)(m3:nj+1,kc+1)
            uint32_t bf_[4][2];
#pragma unroll
            for (int njp = 0; njp < 2; njp++) {
                int row = wn * 32 + njp * 16 + (lm >> 1) * 8 + lr;
                int ch  = kc + (lm & 1);
                uint32_t bd = bBuf + (uint32_t)(row << 7) + ((uint32_t)(ch ^ (row & 7)) << 4);
                LDSM_X4(bf_[njp * 2][0], bf_[njp * 2][1],
                        bf_[njp * 2 + 1][0], bf_[njp * 2 + 1][1], bd);
            }
#pragma unroll
            for (int mi = 0; mi < 4; mi++)
#pragma unroll
                for (int nj = 0; nj < 4; nj++)
                    MMA16816(acc[mi][nj], af[mi][0], af[mi][1], af[mi][2], af[mi][3],
                             bf_[nj][0], bf_[nj][1]);
        }

        if (t + 2 < 48) issue(t + 2, (t + 2) % 3);
    }

    // epilogue: bias + store (fragment layout: lane g=lane>>2 rows, tq=lane&3 col pairs)
    int g  = lane >> 2;
    int tq = lane & 3;
#pragma unroll
    for (int mi = 0; mi < 4; mi++) {
        size_t r0 = (size_t)(m0 + wm * 64 + mi * 16 + g);
        size_t r1 = r0 + 8;
#pragma unroll
        for (int nj = 0; nj < 4; nj++) {
            int c = n0 + wn * 32 + nj * 8 + tq * 2;
            float b0 = bias[c], b1 = bias[c + 1];
            float2 w0 = make_float2(acc[mi][nj][0] + b0, acc[mi][nj][1] + b1);
            float2 w1 = make_float2(acc[mi][nj][2] + b0, acc[mi][nj][3] + b1);
            *(float2*)&C[r0 * N + c] = w0;
            *(float2*)&C[r1 * N + c] = w1;
        }
    }
}

// ---------------------------------------------------------------------------
// prep: build Qcat, Kcat, Vh (head-major).
// ---------------------------------------------------------------------------
__global__ __launch_bounds__(512)
void prep_kernel(const float* __restrict__ Qb, const float* __restrict__ Kb,
                 const float* __restrict__ Vb, const float* __restrict__ J,
                 const float* __restrict__ lamp,
                 float* __restrict__ Qcat, float* __restrict__ Kcat,
                 float* __restrict__ Vh)
{
    __shared__ float Js[4096];
    __shared__ float qn[8][64];

    int h   = blockIdx.y;
    int d   = threadIdx.x;
    int ty  = threadIdx.y;
    int tid = ty * 64 + d;

    for (int i = tid; i < 4096; i += 512) Js[i] = J[h * 4096 + i];

    int tok = blockIdx.x * 8 + ty;
    int b   = tok >> 11;
    int s   = tok & 2047;
    int bh  = (b << 4) + h;

    float q = Qb[(size_t)tok * EMB + h * HD + d];
    float k = Kb[(size_t)tok * EMB + h * HD + d];
    float v = Vb[(size_t)tok * EMB + h * HD + d];
    qn[ty][d] = tanhf(q);
    __syncthreads();

    float accv = 0.f;
#pragma unroll 8
    for (int dd = 0; dd < 64; dd++) accv += qn[ty][dd] * Js[dd * 64 + d];

    float lam = lamp[0];
    size_t base = (size_t)bh * SEQ + s;
    Qcat[base * 128 + d]      = q * 0.125f;
    Qcat[base * 128 + 64 + d] = lam * accv;
    Kcat[base * 128 + d]      = k;
    Kcat[base * 128 + 64 + d] = tanhf(k);
    Vh  [base * 64  + d]      = v;
}

// ---------------------------------------------------------------------------
// flash: causal attention, dk=128, dv=64 (fp32 CUDA cores).
// ---------------------------------------------------------------------------
#define FL_SMEM_FLOATS (128*68 + 128*68 + 64*64 + 64*68)
#define FL_SMEM_BYTES  (FL_SMEM_FLOATS * 4)

__global__ __launch_bounds__(256, 1)
void flash_kernel(const float* __restrict__ Qcat, const float* __restrict__ Kcat,
                  const float* __restrict__ Vh, float* __restrict__ O)
{
    extern __shared__ float sm[];
    float* Qst = sm;
    float* Kst = Qst + 128 * 68;
    float* Vs  = Kst + 128 * 68;
    float* Pst = Vs  + 64 * 64;

    int bh  = blockIdx.y;
    int qt  = gridDim.x - 1 - blockIdx.x;
    int tid = threadIdx.x;
    int tr  = tid >> 4;
    int tc  = tid & 15;

    const float* Qg = Qcat + ((size_t)bh * SEQ + qt * 64) * 128;
    for (int idx = tid; idx < 2048; idx += 256) {
        int r  = idx >> 5;
        int d4 = (idx & 31) << 2;
        float4 v = *(const float4*)&Qg[r * 128 + d4];
        Qst[(d4 + 0) * 68 + r] = v.x;
        Qst[(d4 + 1) * 68 + r] = v.y;
        Qst[(d4 + 2) * 68 + r] = v.z;
        Qst[(d4 + 3) * 68 + r] = v.w;
    }

    float acc[4][4];
#pragma unroll
    for (int i = 0; i < 4; i++)
#pragma unroll
        for (int j = 0; j < 4; j++) acc[i][j] = 0.f;
    float mrow[4] = {-1e30f, -1e30f, -1e30f, -1e30f};
    float lrow[4] = {0.f, 0.f, 0.f, 0.f};

    for (int kt = 0; kt <= qt; kt++) {
        __syncthreads();
        const float* Kg = Kcat + ((size_t)bh * SEQ + kt * 64) * 128;
        const float* Vg = Vh   + ((size_t)bh * SEQ + kt * 64) * 64;
        for (int idx = tid; idx < 2048; idx += 256) {
            int r  = idx >> 5;
            int d4 = (idx & 31) << 2;
            float4 v = *(const float4*)&Kg[r * 128 + d4];
            Kst[(d4 + 0) * 68 + r] = v.x;
            Kst[(d4 + 1) * 68 + r] = v.y;
            Kst[(d4 + 2) * 68 + r] = v.z;
            Kst[(d4 + 3) * 68 + r] = v.w;
        }
        for (int idx = tid; idx < 1024; idx += 256) {
            int j  = idx >> 4;
            int c4 = (idx & 15) << 2;
            *(float4*)&Vs[j * 64 + c4] = *(const float4*)&Vg[j * 64 + c4];
        }
        __syncthreads();

        float s[4][4];
#pragma unroll
        for (int i = 0; i < 4; i++)
#pragma unroll
            for (int j = 0; j < 4; j++) s[i][j] = 0.f;

#pragma unroll 4
        for (int d = 0; d < 128; d++) {
            float4 qv = *(const float4*)&Qst[d * 68 + tr * 4];
            float4 kv = *(const float4*)&Kst[d * 68 + tc * 4];
            float q0 = qv.x, q1 = qv.y, q2 = qv.z, q3 = qv.w;
            float k0 = kv.x, k1 = kv.y, k2 = kv.z, k3 = kv.w;
            s[0][0] += q0 * k0; s[0][1] += q0 * k1; s[0][2] += q0 * k2; s[0][3] += q0 * k3;
            s[1][0] += q1 * k0; s[1][1] += q1 * k1; s[1][2] += q1 * k2; s[1][3] += q1 * k3;
            s[2][0] += q2 * k0; s[2][1] += q2 * k1; s[2][2] += q2 * k2; s[2][3] += q2 * k3;
            s[3][0] += q3 * k0; s[3][1] += q3 * k1; s[3][2] += q3 * k2; s[3][3] += q3 * k3;
        }

        if (kt == qt) {
#pragma unroll
            for (int ri = 0; ri < 4; ri++) {
                int ig = tr * 4 + ri;
#pragma unroll
                for (int jc = 0; jc < 4; jc++) {
                    if (tc * 4 + jc > ig) s[ri][jc] = -1e30f;
                }
            }
        }

#pragma unroll
        for (int ri = 0; ri < 4; ri++) {
            float tm = fmaxf(fmaxf(s[ri][0], s[ri][1]), fmaxf(s[ri][2], s[ri][3]));
            tm = fmaxf(tm, __shfl_xor_sync(0xffffffffu, tm, 1));
            tm = fmaxf(tm, __shfl_xor_sync(0xffffffffu, tm, 2));
            tm = fmaxf(tm, __shfl_xor_sync(0xffffffffu, tm, 4));
            tm = fmaxf(tm, __shfl_xor_sync(0xffffffffu, tm, 8));
            float mnew = fmaxf(mrow[ri], tm);
            float corr = __expf(mrow[ri] - mnew);
            mrow[ri] = mnew;
            float ps = 0.f;
#pragma unroll
            for (int jc = 0; jc < 4; jc++) {
                float p = __expf(s[ri][jc] - mnew);
                s[ri][jc] = p;
                ps += p;
            }
            ps += __shfl_xor_sync(0xffffffffu, ps, 1);
            ps += __shfl_xor_sync(0xffffffffu, ps, 2);
            ps += __shfl_xor_sync(0xffffffffu, ps, 4);
            ps += __shfl_xor_sync(0xffffffffu, ps, 8);
            lrow[ri] = lrow[ri] * corr + ps;
#pragma unroll
            for (int cc = 0; cc < 4; cc++) acc[ri][cc] *= corr;
        }

#pragma unroll
        for (int jc = 0; jc < 4; jc++) {
            float4 w = make_float4(s[0][jc], s[1][jc], s[2][jc], s[3][jc]);
            *(float4*)&Pst[(tc * 4 + jc) * 68 + tr * 4] = w;
        }
        __syncthreads();

#pragma unroll 4
        for (int j = 0; j < 64; j++) {
            float4 pv = *(const float4*)&Pst[j * 68 + tr * 4];
            float4 vv = *(const float4*)&Vs [j * 64 + tc * 4];
            float p0 = pv.x, p1 = pv.y, p2 = pv.z, p3 = pv.w;
            float v0 = vv.x, v1 = vv.y, v2 = vv.z, v3 = vv.w;
            acc[0][0] += p0 * v0; acc[0][1] += p0 * v1; acc[0][2] += p0 * v2; acc[0][3] += p0 * v3;
            acc[1][0] += p1 * v0; acc[1][1] += p1 * v1; acc[1][2] += p1 * v2; acc[1][3] += p1 * v3;
            acc[2][0] += p2 * v0; acc[2][1] += p2 * v1; acc[2][2] += p2 * v2; acc[2][3] += p2 * v3;
            acc[3][0] += p3 * v0; acc[3][1] += p3 * v1; acc[3][2] += p3 * v2; acc[3][3] += p3 * v3;
        }
    }

    int b = bh >> 4;
    int h = bh & 15;
    float* Og = O + ((size_t)(b * SEQ + qt * 64)) * EMB + h * HD;
#pragma unroll
    for (int ri = 0; ri < 4; ri++) {
        float inv = 1.0f / lrow[ri];
        float4 o = make_float4(acc[ri][0] * inv, acc[ri][1] * inv,
                               acc[ri][2] * inv, acc[ri][3] * inv);
        *(float4*)&Og[(size_t)(tr * 4 + ri) * EMB + tc * 4] = o;
    }
}

// ---------------------------------------------------------------------------
// launch
// ---------------------------------------------------------------------------
extern "C" void kernel_launch(void* const* d_in, const int* in_sizes, int n_in,
                              void* d_out, int out_size)
{
    const float* x   = (const float*)d_in[0];
    const float* Wq  = (const float*)d_in[1];
    const float* bq  = (const float*)d_in[2];
    const float* Wk  = (const float*)d_in[3];
    const float* bk  = (const float*)d_in[4];
    const float* Wv  = (const float*)d_in[5];
    const float* bv  = (const float*)d_in[6];
    const float* Wo  = (const float*)d_in[7];
    const float* bo  = (const float*)d_in[8];
    const float* J   = (const float*)d_in[9];
    const float* lam = (const float*)d_in[10];
    float* out = (float*)d_out;

    void* p = nullptr;
    cudaGetSymbolAddress(&p, g_scratch);
    float* scr = (float*)p;
    float* gQ  = scr + OFF_Q;
    float* gK  = scr + OFF_K;
    float* gV  = scr + OFF_V;
    float* gQC = scr + OFF_QC;
    float* gKC = scr + OFF_KC;
    float* gVH = scr + OFF_VH;
    float* gO  = scr + OFF_O;

    cudaGetSymbolAddress(&p, g_bscratch);
    __nv_bfloat16* bscr = (__nv_bfloat16*)p;
    __nv_bfloat16* xh = bscr + BOFF_XH;
    __nv_bfloat16* xl = bscr + BOFF_XL;
    __nv_bfloat16* wt = bscr + BOFF_W;
    __nv_bfloat16* oh = bscr + BOFF_OH;
    __nv_bfloat16* ol = bscr + BOFF_OL;

    const int WSZ = EMB * EMB;
    __nv_bfloat16* wqh = wt + 0 * WSZ; __nv_bfloat16* wql = wt + 1 * WSZ;
    __nv_bfloat16* wkh = wt + 2 * WSZ; __nv_bfloat16* wkl = wt + 3 * WSZ;
    __nv_bfloat16* wvh = wt + 4 * WSZ; __nv_bfloat16* wvl = wt + 5 * WSZ;
    __nv_bfloat16* woh = wt + 6 * WSZ; __nv_bfloat16* wol = wt + 7 * WSZ;

    // conversions
    split_kernel<<<(N_TOK * EMB / 4 + 255) / 256, 256>>>(x, xh, xl, N_TOK * EMB / 4);
    dim3 tg(32, 32), tb(256);
    split_transpose_kernel<<<tg, tb>>>(Wq, wqh, wql);
    split_transpose_kernel<<<tg, tb>>>(Wk, wkh, wkl);
    split_transpose_kernel<<<tg, tb>>>(Wv, wvh, wvl);
    split_transpose_kernel<<<tg, tb>>>(Wo, woh, wol);

    cudaFuncSetAttribute(gemm_bf16c, cudaFuncAttributeMaxDynamicSharedMemorySize, GSMEM);
    dim3 gg(8, 32), gb(256);
    gemm_bf16c<<<gg, gb, GSMEM>>>(xh, xl, wqh, wql, bq, gQ);
    gemm_bf16c<<<gg, gb, GSMEM>>>(xh, xl, wkh, wkl, bk, gK);
    gemm_bf16c<<<gg, gb, GSMEM>>>(xh, xl, wvh, wvl, bv, gV);

    dim3 prep_grid(N_TOK / 8, HEADS), prep_blk(64, 8);
    prep_kernel<<<prep_grid, prep_blk>>>(gQ, gK, gV, J, lam, gQC, gKC, gVH);

    cudaFuncSetAttribute(flash_kernel, cudaFuncAttributeMaxDynamicSharedMemorySize,
                         FL_SMEM_BYTES);
    dim3 fl_grid(SEQ / 64, BH);
    flash_kernel<<<fl_grid, 256, FL_SMEM_BYTES>>>(gQC, gKC, gVH, gO);

    split_kernel<<<(N_TOK * EMB / 4 + 255) / 256, 256>>>(gO, oh, ol, N_TOK * EMB / 4);
    gemm_bf16c<<<gg, gb, GSMEM>>>(oh, ol, woh, wol, bo, out);
}

// round 8
// speedup vs baseline: 4.4064x; 3.0263x over previous
#include <cuda_runtime.h>
#include <cuda_bf16.h>
#include <cuda_fp16.h>
#include <math.h>
#include <stdint.h>

// ---------------------------------------------------------------------------
// QBNN attention. B=2, S=2048, E=1024, H=16, hd=64.
//  0) split: x -> (xh,xl) bf16 ; W* -> transposed (h,l) bf16
//  1) gemm_bf16c: 3-pass compensated bf16 mma.sync (ldmatrix/SW128/cp.async)
//  2) prep: Qcat/Kcat fp16 [bh][s][128], Vt fp16 [bh][d][s]
//  3) flash16: causal attention on fp16 tensor cores, fp32 softmax
//  4) split gO, gemm_bf16c -> out
// ---------------------------------------------------------------------------

#define N_TOK   4096
#define EMB     1024
#define HEADS   16
#define HD      64
#define SEQ     2048
#define BH      32

// fp32 scratch
#define OFF_Q   0
#define OFF_K   (OFF_Q  + N_TOK*EMB)
#define OFF_V   (OFF_K  + N_TOK*EMB)
#define OFF_O   (OFF_V  + N_TOK*EMB)
#define SCRATCH_FLOATS (OFF_O + N_TOK*EMB)
__device__ float g_scratch[SCRATCH_FLOATS];

// bf16 scratch
#define BOFF_XH   0
#define BOFF_XL   (BOFF_XH + N_TOK*EMB)
#define BOFF_W    (BOFF_XL + N_TOK*EMB)
#define BOFF_OH   (BOFF_W  + 8*EMB*EMB)
#define BOFF_OL   (BOFF_OH + N_TOK*EMB)
#define BSCRATCH  (BOFF_OL + N_TOK*EMB)
__device__ __nv_bfloat16 g_bscratch[BSCRATCH];

// fp16 scratch (attention operands)
#define HOFF_QC  0
#define HOFF_KC  (HOFF_QC + BH*SEQ*128)
#define HOFF_VT  (HOFF_KC + BH*SEQ*128)
#define HSCRATCH (HOFF_VT + BH*64*SEQ)
__device__ __half g_hscratch[HSCRATCH];

// ---------------------------------------------------------------------------
// split: fp32 -> hi/lo bf16
// ---------------------------------------------------------------------------
__global__ __launch_bounds__(256)
void split_kernel(const float* __restrict__ src, __nv_bfloat16* __restrict__ h,
                  __nv_bfloat16* __restrict__ l, int n4)
{
    int i = blockIdx.x * blockDim.x + threadIdx.x;
    if (i >= n4) return;
    float4 v = ((const float4*)src)[i];
    float va[4] = {v.x, v.y, v.z, v.w};
    __nv_bfloat16 hh[4], ll[4];
#pragma unroll
    for (int j = 0; j < 4; j++) {
        hh[j] = __float2bfloat16_rn(va[j]);
        ll[j] = __float2bfloat16_rn(va[j] - __bfloat162float(hh[j]));
    }
    ((uint2*)h)[i] = *(uint2*)hh;
    ((uint2*)l)[i] = *(uint2*)ll;
}

// ---------------------------------------------------------------------------
// split+transpose: W[k][n] fp32 -> Wt{h,l}[n][k] bf16
// ---------------------------------------------------------------------------
__global__ __launch_bounds__(256)
void split_transpose_kernel(const float* __restrict__ W,
                            __nv_bfloat16* __restrict__ th,
                            __nv_bfloat16* __restrict__ tl)
{
    __shared__ float tile[32][33];
    int k0 = blockIdx.y * 32;
    int n0 = blockIdx.x * 32;
    int tx = threadIdx.x & 31;
    int ty = threadIdx.x >> 5;
#pragma unroll
    for (int j = 0; j < 4; j++)
        tile[ty + j * 8][tx] = W[(size_t)(k0 + ty + j * 8) * EMB + n0 + tx];
    __syncthreads();
#pragma unroll
    for (int j = 0; j < 4; j++) {
        int n = ty + j * 8;
        float v = tile[tx][n];
        __nv_bfloat16 h = __float2bfloat16_rn(v);
        __nv_bfloat16 l = __float2bfloat16_rn(v - __bfloat162float(h));
        th[(size_t)(n0 + n) * EMB + k0 + tx] = h;
        tl[(size_t)(n0 + n) * EMB + k0 + tx] = l;
    }
}

// ---------------------------------------------------------------------------
// mma / ldmatrix / cp.async helpers
// ---------------------------------------------------------------------------
#define MMA16816(d, a0, a1, a2, a3, b0, b1)                                  \
    asm volatile(                                                            \
        "mma.sync.aligned.m16n8k16.row.col.f32.bf16.bf16.f32 "               \
        "{%0,%1,%2,%3}, {%4,%5,%6,%7}, {%8,%9}, {%0,%1,%2,%3};"              \
        : "+f"(d[0]), "+f"(d[1]), "+f"(d[2]), "+f"(d[3])                     \
        : "r"(a0), "r"(a1), "r"(a2), "r"(a3), "r"(b0), "r"(b1))

#define MMA16816H(d, a0, a1, a2, a3, b0, b1)                                 \
    asm volatile(                                                            \
        "mma.sync.aligned.m16n8k16.row.col.f32.f16.f16.f32 "                 \
        "{%0,%1,%2,%3}, {%4,%5,%6,%7}, {%8,%9}, {%0,%1,%2,%3};"              \
        : "+f"(d[0]), "+f"(d[1]), "+f"(d[2]), "+f"(d[3])                     \
        : "r"(a0), "r"(a1), "r"(a2), "r"(a3), "r"(b0), "r"(b1))

#define LDSM_X4(r0, r1, r2, r3, addr)                                        \
    asm volatile("ldmatrix.sync.aligned.m8n8.x4.shared.b16 {%0,%1,%2,%3}, [%4];" \
        : "=r"(r0), "=r"(r1), "=r"(r2), "=r"(r3) : "r"(addr))

__device__ __forceinline__ void cp16s(uint32_t smem_dst, const void* gmem_src)
{
    asm volatile("cp.async.cg.shared.global [%0], [%1], 16;"
                 :: "r"(smem_dst), "l"(gmem_src));
}

// ---------------------------------------------------------------------------
// Compensated bf16 tensor-core GEMM (unchanged from passing R6 version).
// ---------------------------------------------------------------------------
#define GSTAGE  32768
#define GSMEM   (3 * GSTAGE)

__global__ __launch_bounds__(256, 2)
void gemm_bf16c(const __nv_bfloat16* __restrict__ Ah, const __nv_bfloat16* __restrict__ Al,
                const __nv_bfloat16* __restrict__ Bh, const __nv_bfloat16* __restrict__ Bl,
                const float* __restrict__ bias, float* __restrict__ C)
{
    extern __shared__ __align__(1024) char smem[];
    const int K = 1024, N = 1024;
    uint32_t sbase;
    asm("{ .reg .u64 t; cvta.to.shared.u64 t, %1; cvt.u32.u64 %0, t; }"
        : "=r"(sbase) : "l"(smem));

    int tid  = threadIdx.x;
    int warp = tid >> 5;
    int lane = tid & 31;
    int wm   = warp & 1;
    int wn   = warp >> 1;
    int m0   = blockIdx.y * 128;
    int n0   = blockIdx.x * 128;

    const __nv_bfloat16* pA[3] = {Ah, Ah, Al};
    const __nv_bfloat16* pB[3] = {Bh, Bl, Bh};

    float acc[4][4][4];
#pragma unroll
    for (int mi = 0; mi < 4; mi++)
#pragma unroll
        for (int nj = 0; nj < 4; nj++)
#pragma unroll
            for (int t = 0; t < 4; t++) acc[mi][nj][t] = 0.f;

    auto issue = [&](int chunk, int stg) {
        int p  = chunk >> 4;
        int k0 = (chunk & 15) << 6;
        const __nv_bfloat16* Ap = pA[p] + (size_t)m0 * K + k0;
        const __nv_bfloat16* Bp = pB[p] + (size_t)n0 * K + k0;
        uint32_t aBuf = sbase + stg * GSTAGE;
        uint32_t bBuf = aBuf + 16384;
#pragma unroll
        for (int i = 0; i < 4; i++) {
            int idx = tid + i * 256;
            int r   = idx >> 3;
            int c   = idx & 7;
            uint32_t sw = (uint32_t)(r << 7) | ((uint32_t)(c ^ (r & 7)) << 4);
            cp16s(aBuf + sw, Ap + (size_t)r * K + c * 8);
            cp16s(bBuf + sw, Bp + (size_t)r * K + c * 8);
        }
        asm volatile("cp.async.commit_group;");
    };

    issue(0, 0);
    issue(1, 1);

    int lm  = lane >> 3;
    int lr  = lane & 7;

    for (int t = 0; t < 48; t++) {
        int stg = t % 3;
        if (t < 47) asm volatile("cp.async.wait_group 1;");
        else        asm volatile("cp.async.wait_group 0;");
        __syncthreads();

        uint32_t aBuf = sbase + stg * GSTAGE;
        uint32_t bBuf = aBuf + 16384;

#pragma unroll
        for (int kk = 0; kk < 64; kk += 16) {
            int kc = kk >> 3;
            uint32_t af[4][4];
#pragma unroll
            for (int mi = 0; mi < 4; mi++) {
                int row = wm * 64 + mi * 16 + (lm & 1) * 8 + lr;
                int ch  = kc + (lm >> 1);
                uint32_t ad = aBuf + (uint32_t)(row << 7) + ((uint32_t)(ch ^ (row & 7)) << 4);
                LDSM_X4(af[mi][0], af[mi][1], af[mi][2], af[mi][3], ad);
            }
            uint32_t bf_[4][2];
#pragma unroll
            for (int njp = 0; njp < 2; njp++) {
                int row = wn * 32 + njp * 16 + (lm >> 1) * 8 + lr;
                int ch  = kc + (lm & 1);
                uint32_t bd = bBuf + (uint32_t)(row << 7) + ((uint32_t)(ch ^ (row & 7)) << 4);
                LDSM_X4(bf_[njp * 2][0], bf_[njp * 2][1],
                        bf_[njp * 2 + 1][0], bf_[njp * 2 + 1][1], bd);
            }
#pragma unroll
            for (int mi = 0; mi < 4; mi++)
#pragma unroll
                for (int nj = 0; nj < 4; nj++)
                    MMA16816(acc[mi][nj], af[mi][0], af[mi][1], af[mi][2], af[mi][3],
                             bf_[nj][0], bf_[nj][1]);
        }

        if (t + 2 < 48) issue(t + 2, (t + 2) % 3);
    }

    int g  = lane >> 2;
    int tq = lane & 3;
#pragma unroll
    for (int mi = 0; mi < 4; mi++) {
        size_t r0 = (size_t)(m0 + wm * 64 + mi * 16 + g);
        size_t r1 = r0 + 8;
#pragma unroll
        for (int nj = 0; nj < 4; nj++) {
            int c = n0 + wn * 32 + nj * 8 + tq * 2;
            float b0 = bias[c], b1 = bias[c + 1];
            float2 w0 = make_float2(acc[mi][nj][0] + b0, acc[mi][nj][1] + b1);
            float2 w1 = make_float2(acc[mi][nj][2] + b0, acc[mi][nj][3] + b1);
            *(float2*)&C[r0 * N + c] = w0;
            *(float2*)&C[r1 * N + c] = w1;
        }
    }
}

// ---------------------------------------------------------------------------
// prep: fp16 Qcat/Kcat [bh][s][128], Vt [bh][d][s]
// ---------------------------------------------------------------------------
__global__ __launch_bounds__(512)
void prep_kernel(const float* __restrict__ Qb, const float* __restrict__ Kb,
                 const float* __restrict__ Vb, const float* __restrict__ J,
                 const float* __restrict__ lamp,
                 __half* __restrict__ Qc, __half* __restrict__ Kc,
                 __half* __restrict__ Vt)
{
    __shared__ float Js[4096];
    __shared__ float qn[8][64];

    int h   = blockIdx.y;
    int d   = threadIdx.x;
    int ty  = threadIdx.y;
    int tid = ty * 64 + d;

    for (int i = tid; i < 4096; i += 512) Js[i] = J[h * 4096 + i];

    int tok = blockIdx.x * 8 + ty;
    int b   = tok >> 11;
    int s   = tok & 2047;
    int bh  = (b << 4) + h;

    float q = Qb[(size_t)tok * EMB + h * HD + d];
    float k = Kb[(size_t)tok * EMB + h * HD + d];
    float v = Vb[(size_t)tok * EMB + h * HD + d];
    qn[ty][d] = tanhf(q);
    __syncthreads();

    float accv = 0.f;
#pragma unroll 8
    for (int dd = 0; dd < 64; dd++) accv += qn[ty][dd] * Js[dd * 64 + d];

    float lam = lamp[0];
    size_t base = (size_t)bh * SEQ + s;
    Qc[base * 128 + d]      = __float2half(q * 0.125f);
    Qc[base * 128 + 64 + d] = __float2half(lam * accv);
    Kc[base * 128 + d]      = __float2half(k);
    Kc[base * 128 + 64 + d] = __float2half(tanhf(k));
    Vt[((size_t)bh * 64 + d) * SEQ + s] = __float2half(v);
}

// ---------------------------------------------------------------------------
// flash16: causal attention, fp16 tensor cores.
// CTA: 128 q-rows, 8 warps x 16 rows. kt tiles of 64 kv.
// smem: Q 32KB (two 128x64 halves) + 2 stages x (K 16KB + V 8KB) = 80KB.
// ---------------------------------------------------------------------------
#define FLQ_BYTES  32768
#define FLSTAGE    24576
#define FL16_SMEM  (FLQ_BYTES + 2 * FLSTAGE)

__global__ __launch_bounds__(256, 1)
void flash16_kernel(const __half* __restrict__ Qc, const __half* __restrict__ Kc,
                    const __half* __restrict__ Vt, float* __restrict__ O)
{
    extern __shared__ __align__(1024) char smem[];
    uint32_t sbase;
    asm("{ .reg .u64 t; cvta.to.shared.u64 t, %1; cvt.u32.u64 %0, t; }"
        : "=r"(sbase) : "l"(smem));

    int tid  = threadIdx.x;
    int w    = tid >> 5;
    int lane = tid & 31;
    int lm   = lane >> 3;
    int lr   = lane & 7;
    int g    = lane >> 2;
    int tq   = lane & 3;

    int bh    = blockIdx.y;
    int b     = bh >> 4;
    int h     = bh & 15;
    int qtile = (int)gridDim.x - 1 - (int)blockIdx.x;   // heavy first
    int qt0   = qtile * 128;
    int nkt   = 2 * qtile + 2;

    // ---- issue Q load (group 0) ----
    const __half* Qg = Qc + ((size_t)bh * SEQ + qt0) * 128;
#pragma unroll
    for (int i = 0; i < 8; i++) {
        int idx = tid + i * 256;
        int r   = idx >> 4;
        int ch  = idx & 15;
        uint32_t dst = sbase + (uint32_t)(ch >> 3) * 16384
                     + (uint32_t)(r << 7) + ((uint32_t)((ch & 7) ^ (r & 7)) << 4);
        cp16s(dst, Qg + (size_t)r * 128 + ch * 8);
    }
    asm volatile("cp.async.commit_group;");

    auto issueKV = [&](int kt, int s) {
        uint32_t kb = sbase + FLQ_BYTES + (uint32_t)s * FLSTAGE;
        uint32_t vb = kb + 16384;
        const __half* Kg = Kc + ((size_t)bh * SEQ + kt * 64) * 128;
        const __half* Vg = Vt + (size_t)bh * 64 * SEQ + kt * 64;
#pragma unroll
        for (int i = 0; i < 4; i++) {
            int idx = tid + i * 256;
            int r   = idx >> 4;
            int ch  = idx & 15;
            uint32_t dst = kb + (uint32_t)(ch >> 3) * 8192
                         + (uint32_t)(r << 7) + ((uint32_t)((ch & 7) ^ (r & 7)) << 4);
            cp16s(dst, Kg + (size_t)r * 128 + ch * 8);
        }
#pragma unroll
        for (int i = 0; i < 2; i++) {
            int idx = tid + i * 256;
            int r   = idx >> 3;
            int c   = idx & 7;
            uint32_t dst = vb + (uint32_t)(r << 7) + ((uint32_t)(c ^ (r & 7)) << 4);
            cp16s(dst, Vg + (size_t)r * SEQ + c * 8);
        }
        asm volatile("cp.async.commit_group;");
    };

    issueKV(0, 0);
    issueKV(1, 1);

    // wait Q (oldest of 3 pending groups), then load Q fragments once
    asm volatile("cp.async.wait_group 2;");
    __syncthreads();

    uint32_t qf[8][4];
#pragma unroll
    for (int ks = 0; ks < 8; ks++) {
        int half = ks >> 2;
        int kc   = (ks & 3) * 2 + (lm >> 1);
        int row  = w * 16 + (lm & 1) * 8 + lr;
        uint32_t ad = sbase + (uint32_t)half * 16384
                    + (uint32_t)(row << 7) + ((uint32_t)(kc ^ (row & 7)) << 4);
        LDSM_X4(qf[ks][0], qf[ks][1], qf[ks][2], qf[ks][3], ad);
    }

    float oacc[8][4];
#pragma unroll
    for (int nt = 0; nt < 8; nt++)
#pragma unroll
        for (int t = 0; t < 4; t++) oacc[nt][t] = 0.f;
    float mrow[2] = {-1e30f, -1e30f};
    float lrow[2] = {0.f, 0.f};

    int qrow0 = qt0 + w * 16;
    int r0g   = qrow0 + g;

    for (int kt = 0; kt < nkt; kt++) {
        int s_ = kt & 1;
        if (kt + 1 < nkt) asm volatile("cp.async.wait_group 1;");
        else              asm volatile("cp.async.wait_group 0;");
        __syncthreads();

        uint32_t kb = sbase + FLQ_BYTES + (uint32_t)s_ * FLSTAGE;
        uint32_t vb = kb + 16384;

        float sacc[8][4];
#pragma unroll
        for (int nt = 0; nt < 8; nt++)
#pragma unroll
            for (int t = 0; t < 4; t++) sacc[nt][t] = 0.f;

        // S = Qcat @ Kcat^T
#pragma unroll
        for (int ks = 0; ks < 8; ks++) {
            int half = ks >> 2;
            int kc   = (ks & 3) * 2 + (lm & 1);
            uint32_t kf[8][2];
#pragma unroll
            for (int nb = 0; nb < 4; nb++) {
                int row = nb * 16 + (lm >> 1) * 8 + lr;
                uint32_t ad = kb + (uint32_t)half * 8192
                            + (uint32_t)(row << 7) + ((uint32_t)(kc ^ (row & 7)) << 4);
                LDSM_X4(kf[nb * 2][0], kf[nb * 2][1],
                        kf[nb * 2 + 1][0], kf[nb * 2 + 1][1], ad);
            }
#pragma unroll
            for (int nt = 0; nt < 8; nt++)
                MMA16816H(sacc[nt], qf[ks][0], qf[ks][1], qf[ks][2], qf[ks][3],
                          kf[nt][0], kf[nt][1]);
        }

        // causal mask (diagonal-straddling tiles only)
        if (kt * 64 + 63 > qrow0) {
#pragma unroll
            for (int nt = 0; nt < 8; nt++) {
                int c0 = kt * 64 + nt * 8 + 2 * tq;
                if (c0     > r0g)     sacc[nt][0] = -1e30f;
                if (c0 + 1 > r0g)     sacc[nt][1] = -1e30f;
                if (c0     > r0g + 8) sacc[nt][2] = -1e30f;
                if (c0 + 1 > r0g + 8) sacc[nt][3] = -1e30f;
            }
        }

        // online softmax per row half (hh=0: rows g; hh=1: rows g+8)
#pragma unroll
        for (int hh = 0; hh < 2; hh++) {
            float tm = -1e30f;
#pragma unroll
            for (int nt = 0; nt < 8; nt++)
                tm = fmaxf(tm, fmaxf(sacc[nt][2 * hh], sacc[nt][2 * hh + 1]));
            tm = fmaxf(tm, __shfl_xor_sync(0xffffffffu, tm, 1));
            tm = fmaxf(tm, __shfl_xor_sync(0xffffffffu, tm, 2));
            float mnew = fmaxf(mrow[hh], tm);
            float corr = __expf(mrow[hh] - mnew);
            mrow[hh] = mnew;
            float ps = 0.f;
#pragma unroll
            for (int nt = 0; nt < 8; nt++) {
                float e0 = __expf(sacc[nt][2 * hh]     - mnew);
                float e1 = __expf(sacc[nt][2 * hh + 1] - mnew);
                sacc[nt][2 * hh]     = e0;
                sacc[nt][2 * hh + 1] = e1;
                ps += e0 + e1;
            }
            ps += __shfl_xor_sync(0xffffffffu, ps, 1);
            ps += __shfl_xor_sync(0xffffffffu, ps, 2);
            lrow[hh] = lrow[hh] * corr + ps;
#pragma unroll
            for (int nt = 0; nt < 8; nt++) {
                oacc[nt][2 * hh]     *= corr;
                oacc[nt][2 * hh + 1] *= corr;
            }
        }

        // P fragments (C-layout == A-layout), fp32 -> half2
        uint32_t pf[4][4];
#pragma unroll
        for (int kc16 = 0; kc16 < 4; kc16++) {
            __half2 h0 = __floats2half2_rn(sacc[2 * kc16][0],     sacc[2 * kc16][1]);
            __half2 h1 = __floats2half2_rn(sacc[2 * kc16][2],     sacc[2 * kc16][3]);
            __half2 h2 = __floats2half2_rn(sacc[2 * kc16 + 1][0], sacc[2 * kc16 + 1][1]);
            __half2 h3 = __floats2half2_rn(sacc[2 * kc16 + 1][2], sacc[2 * kc16 + 1][3]);
            pf[kc16][0] = *(uint32_t*)&h0;
            pf[kc16][1] = *(uint32_t*)&h1;
            pf[kc16][2] = *(uint32_t*)&h2;
            pf[kc16][3] = *(uint32_t*)&h3;
        }

        // O += P @ V  (V stored [dv][kv] in smem)
#pragma unroll
        for (int kc16 = 0; kc16 < 4; kc16++) {
            int kc = kc16 * 2 + (lm & 1);
            uint32_t vf[8][2];
#pragma unroll
            for (int nb = 0; nb < 4; nb++) {
                int row = nb * 16 + (lm >> 1) * 8 + lr;
                uint32_t ad = vb + (uint32_t)(row << 7)
                            + ((uint32_t)(kc ^ (row & 7)) << 4);
                LDSM_X4(vf[nb * 2][0], vf[nb * 2][1],
                        vf[nb * 2 + 1][0], vf[nb * 2 + 1][1], ad);
            }
#pragma unroll
            for (int nt = 0; nt < 8; nt++)
                MMA16816H(oacc[nt], pf[kc16][0], pf[kc16][1], pf[kc16][2], pf[kc16][3],
                          vf[nt][0], vf[nt][1]);
        }

        __syncthreads();
        if (kt + 2 < nkt) issueKV(kt + 2, s_);
    }

    // epilogue
    float inv0 = 1.0f / lrow[0];
    float inv1 = 1.0f / lrow[1];
    size_t rt0 = (size_t)(b * SEQ + qt0 + w * 16 + g);
    float* O0 = O + rt0 * EMB + h * 64;
    float* O1 = O0 + (size_t)8 * EMB;
#pragma unroll
    for (int nt = 0; nt < 8; nt++) {
        int c = nt * 8 + 2 * tq;
        *(float2*)&O0[c] = make_float2(oacc[nt][0] * inv0, oacc[nt][1] * inv0);
        *(float2*)&O1[c] = make_float2(oacc[nt][2] * inv1, oacc[nt][3] * inv1);
    }
}

// ---------------------------------------------------------------------------
// launch
// ---------------------------------------------------------------------------
extern "C" void kernel_launch(void* const* d_in, const int* in_sizes, int n_in,
                              void* d_out, int out_size)
{
    const float* x   = (const float*)d_in[0];
    const float* Wq  = (const float*)d_in[1];
    const float* bq  = (const float*)d_in[2];
    const float* Wk  = (const float*)d_in[3];
    const float* bk  = (const float*)d_in[4];
    const float* Wv  = (const float*)d_in[5];
    const float* bv  = (const float*)d_in[6];
    const float* Wo  = (const float*)d_in[7];
    const float* bo  = (const float*)d_in[8];
    const float* J   = (const float*)d_in[9];
    const float* lam = (const float*)d_in[10];
    float* out = (float*)d_out;

    void* p = nullptr;
    cudaGetSymbolAddress(&p, g_scratch);
    float* scr = (float*)p;
    float* gQ  = scr + OFF_Q;
    float* gK  = scr + OFF_K;
    float* gV  = scr + OFF_V;
    float* gO  = scr + OFF_O;

    cudaGetSymbolAddress(&p, g_bscratch);
    __nv_bfloat16* bscr = (__nv_bfloat16*)p;
    __nv_bfloat16* xh = bscr + BOFF_XH;
    __nv_bfloat16* xl = bscr + BOFF_XL;
    __nv_bfloat16* wt = bscr + BOFF_W;
    __nv_bfloat16* oh = bscr + BOFF_OH;
    __nv_bfloat16* ol = bscr + BOFF_OL;

    cudaGetSymbolAddress(&p, g_hscratch);
    __half* hscr = (__half*)p;
    __half* hQC = hscr + HOFF_QC;
    __half* hKC = hscr + HOFF_KC;
    __half* hVT = hscr + HOFF_VT;

    const int WSZ = EMB * EMB;
    __nv_bfloat16* wqh = wt + 0 * WSZ; __nv_bfloat16* wql = wt + 1 * WSZ;
    __nv_bfloat16* wkh = wt + 2 * WSZ; __nv_bfloat16* wkl = wt + 3 * WSZ;
    __nv_bfloat16* wvh = wt + 4 * WSZ; __nv_bfloat16* wvl = wt + 5 * WSZ;
    __nv_bfloat16* woh = wt + 6 * WSZ; __nv_bfloat16* wol = wt + 7 * WSZ;

    // conversions
    split_kernel<<<(N_TOK * EMB / 4 + 255) / 256, 256>>>(x, xh, xl, N_TOK * EMB / 4);
    dim3 tg(32, 32), tb(256);
    split_transpose_kernel<<<tg, tb>>>(Wq, wqh, wql);
    split_transpose_kernel<<<tg, tb>>>(Wk, wkh, wkl);
    split_transpose_kernel<<<tg, tb>>>(Wv, wvh, wvl);
    split_transpose_kernel<<<tg, tb>>>(Wo, woh, wol);

    cudaFuncSetAttribute(gemm_bf16c, cudaFuncAttributeMaxDynamicSharedMemorySize, GSMEM);
    dim3 gg(8, 32), gb(256);
    gemm_bf16c<<<gg, gb, GSMEM>>>(xh, xl, wqh, wql, bq, gQ);
    gemm_bf16c<<<gg, gb, GSMEM>>>(xh, xl, wkh, wkl, bk, gK);
    gemm_bf16c<<<gg, gb, GSMEM>>>(xh, xl, wvh, wvl, bv, gV);

    dim3 prep_grid(N_TOK / 8, HEADS), prep_blk(64, 8);
    prep_kernel<<<prep_grid, prep_blk>>>(gQ, gK, gV, J, lam, hQC, hKC, hVT);

    cudaFuncSetAttribute(flash16_kernel, cudaFuncAttributeMaxDynamicSharedMemorySize,
                         FL16_SMEM);
    dim3 fl_grid(SEQ / 128, BH);
    flash16_kernel<<<fl_grid, 256, FL16_SMEM>>>(hQC, hKC, hVT, gO);

    split_kernel<<<(N_TOK * EMB / 4 + 255) / 256, 256>>>(gO, oh, ol, N_TOK * EMB / 4);
    gemm_bf16c<<<gg, gb, GSMEM>>>(oh, ol, woh, wol, bo, out);
}

// round 9
// speedup vs baseline: 6.8749x; 1.5602x over previous
#include <cuda_runtime.h>
#include <cuda_fp16.h>
#include <math.h>
#include <stdint.h>

// ---------------------------------------------------------------------------
// QBNN attention, all-fp16 tensor-core pipeline. B=2, S=2048, E=1024, H=16, hd=64.
//  0) convert: x -> fp16 ; W* -> transposed fp16
//  1) gemm_fp16: Q,K,V = x@W + b  (single-pass fp16 mma, fp16 out)
//  2) prep: Qcat/Kcat fp16 [bh][s][128], Vt fp16 [bh][d][s]
//  3) flash16: causal attention on fp16 tensor cores, fp32 softmax, fp16 O
//  4) gemm_fp16: out = O@Wo + bo (fp32 out)
// ---------------------------------------------------------------------------

#define N_TOK   4096
#define EMB     1024
#define HEADS   16
#define HD      64
#define SEQ     2048
#define BH      32

// fp16 scratch arena
#define HX    0
#define HW    (HX   + N_TOK*EMB)          // 4 transposed weights, 1M each
#define HQ    (HW   + 4*EMB*EMB)
#define HK    (HQ   + N_TOK*EMB)
#define HV    (HK   + N_TOK*EMB)
#define HQC   (HV   + N_TOK*EMB)          // [BH][SEQ][128]
#define HKC   (HQC  + BH*SEQ*128)
#define HVT   (HKC  + BH*SEQ*128)         // [BH][64][SEQ]
#define HO    (HVT  + BH*64*SEQ)          // [N_TOK][EMB]
#define HTOTAL (HO  + N_TOK*EMB)
__device__ __half g_hscratch[HTOTAL];

// ---------------------------------------------------------------------------
// convert: fp32 -> fp16 elementwise
// ---------------------------------------------------------------------------
__global__ __launch_bounds__(256)
void convert_kernel(const float* __restrict__ src, __half* __restrict__ dst, int n4)
{
    int i = blockIdx.x * blockDim.x + threadIdx.x;
    if (i >= n4) return;
    float4 v = ((const float4*)src)[i];
    __half2 h0 = __floats2half2_rn(v.x, v.y);
    __half2 h1 = __floats2half2_rn(v.z, v.w);
    uint2 w;
    w.x = *(uint32_t*)&h0;
    w.y = *(uint32_t*)&h1;
    ((uint2*)dst)[i] = w;
}

// ---------------------------------------------------------------------------
// transpose+convert: W[k][n] fp32 -> Wt[n][k] fp16
// ---------------------------------------------------------------------------
__global__ __launch_bounds__(256)
void transpose_convert_kernel(const float* __restrict__ W, __half* __restrict__ T)
{
    __shared__ float tile[32][33];
    int k0 = blockIdx.y * 32;
    int n0 = blockIdx.x * 32;
    int tx = threadIdx.x & 31;
    int ty = threadIdx.x >> 5;
#pragma unroll
    for (int j = 0; j < 4; j++)
        tile[ty + j * 8][tx] = W[(size_t)(k0 + ty + j * 8) * EMB + n0 + tx];
    __syncthreads();
#pragma unroll
    for (int j = 0; j < 4; j++) {
        int n = ty + j * 8;
        T[(size_t)(n0 + n) * EMB + k0 + tx] = __float2half(tile[tx][n]);
    }
}

// ---------------------------------------------------------------------------
// mma / ldmatrix / cp.async helpers
// ---------------------------------------------------------------------------
#define MMA16816H(d, a0, a1, a2, a3, b0, b1)                                 \
    asm volatile(                                                            \
        "mma.sync.aligned.m16n8k16.row.col.f32.f16.f16.f32 "                 \
        "{%0,%1,%2,%3}, {%4,%5,%6,%7}, {%8,%9}, {%0,%1,%2,%3};"              \
        : "+f"(d[0]), "+f"(d[1]), "+f"(d[2]), "+f"(d[3])                     \
        : "r"(a0), "r"(a1), "r"(a2), "r"(a3), "r"(b0), "r"(b1))

#define LDSM_X4(r0, r1, r2, r3, addr)                                        \
    asm volatile("ldmatrix.sync.aligned.m8n8.x4.shared.b16 {%0,%1,%2,%3}, [%4];" \
        : "=r"(r0), "=r"(r1), "=r"(r2), "=r"(r3) : "r"(addr))

__device__ __forceinline__ void cp16s(uint32_t smem_dst, const void* gmem_src)
{
    asm volatile("cp.async.cg.shared.global [%0], [%1], 16;"
                 :: "r"(smem_dst), "l"(gmem_src));
}

// ---------------------------------------------------------------------------
// Single-pass fp16 tensor-core GEMM.
// C[4096x1024] = A@W + bias. A fp16 [m][k]; W fp16 transposed [n][k].
// CTA 128x128, 8 warps (2 wm x 4 wn), warp 64x32, BK=64,
// SW128 swizzle, 3-stage cp.async, ldmatrix.x4.
// half_out: 1 -> fp16 C, 0 -> fp32 C.
// ---------------------------------------------------------------------------
#define GSTAGE  32768
#define GSMEM   (3 * GSTAGE)

__global__ __launch_bounds__(256, 2)
void gemm_fp16(const __half* __restrict__ A, const __half* __restrict__ Bt,
               const float* __restrict__ bias, void* __restrict__ Cout, int half_out)
{
    extern __shared__ __align__(1024) char smem[];
    const int K = 1024, N = 1024;
    uint32_t sbase;
    asm("{ .reg .u64 t; cvta.to.shared.u64 t, %1; cvt.u32.u64 %0, t; }"
        : "=r"(sbase) : "l"(smem));

    int tid  = threadIdx.x;
    int warp = tid >> 5;
    int lane = tid & 31;
    int wm   = warp & 1;
    int wn   = warp >> 1;
    int m0   = blockIdx.y * 128;
    int n0   = blockIdx.x * 128;

    float acc[4][4][4];
#pragma unroll
    for (int mi = 0; mi < 4; mi++)
#pragma unroll
        for (int nj = 0; nj < 4; nj++)
#pragma unroll
            for (int t = 0; t < 4; t++) acc[mi][nj][t] = 0.f;

    auto issue = [&](int chunk, int stg) {
        int k0 = chunk << 6;
        const __half* Ap = A  + (size_t)m0 * K + k0;
        const __half* Bp = Bt + (size_t)n0 * K + k0;
        uint32_t aBuf = sbase + stg * GSTAGE;
        uint32_t bBuf = aBuf + 16384;
#pragma unroll
        for (int i = 0; i < 4; i++) {
            int idx = tid + i * 256;
            int r   = idx >> 3;
            int c   = idx & 7;
            uint32_t sw = (uint32_t)(r << 7) | ((uint32_t)(c ^ (r & 7)) << 4);
            cp16s(aBuf + sw, Ap + (size_t)r * K + c * 8);
            cp16s(bBuf + sw, Bp + (size_t)r * K + c * 8);
        }
        asm volatile("cp.async.commit_group;");
    };

    issue(0, 0);
    issue(1, 1);

    int lm  = lane >> 3;
    int lr  = lane & 7;

    for (int t = 0; t < 16; t++) {
        int stg = t % 3;
        if (t < 15) asm volatile("cp.async.wait_group 1;");
        else        asm volatile("cp.async.wait_group 0;");
        __syncthreads();

        uint32_t aBuf = sbase + stg * GSTAGE;
        uint32_t bBuf = aBuf + 16384;

#pragma unroll
        for (int kk = 0; kk < 64; kk += 16) {
            int kc = kk >> 3;
            uint32_t af[4][4];
#pragma unroll
            for (int mi = 0; mi < 4; mi++) {
                int row = wm * 64 + mi * 16 + (lm & 1) * 8 + lr;
                int ch  = kc + (lm >> 1);
                uint32_t ad = aBuf + (uint32_t)(row << 7) + ((uint32_t)(ch ^ (row & 7)) << 4);
                LDSM_X4(af[mi][0], af[mi][1], af[mi][2], af[mi][3], ad);
            }
            uint32_t bf_[4][2];
#pragma unroll
            for (int njp = 0; njp < 2; njp++) {
                int row = wn * 32 + njp * 16 + (lm >> 1) * 8 + lr;
                int ch  = kc + (lm & 1);
                uint32_t bd = bBuf + (uint32_t)(row << 7) + ((uint32_t)(ch ^ (row & 7)) << 4);
                LDSM_X4(bf_[njp * 2][0], bf_[njp * 2][1],
                        bf_[njp * 2 + 1][0], bf_[njp * 2 + 1][1], bd);
            }
#pragma unroll
            for (int mi = 0; mi < 4; mi++)
#pragma unroll
                for (int nj = 0; nj < 4; nj++)
                    MMA16816H(acc[mi][nj], af[mi][0], af[mi][1], af[mi][2], af[mi][3],
                              bf_[nj][0], bf_[nj][1]);
        }

        if (t + 2 < 16) issue(t + 2, (t + 2) % 3);
    }

    int g  = lane >> 2;
    int tq = lane & 3;
#pragma unroll
    for (int mi = 0; mi < 4; mi++) {
        size_t r0 = (size_t)(m0 + wm * 64 + mi * 16 + g);
        size_t r1 = r0 + 8;
#pragma unroll
        for (int nj = 0; nj < 4; nj++) {
            int c = n0 + wn * 32 + nj * 8 + tq * 2;
            float b0 = bias[c], b1 = bias[c + 1];
            float v00 = acc[mi][nj][0] + b0, v01 = acc[mi][nj][1] + b1;
            float v10 = acc[mi][nj][2] + b0, v11 = acc[mi][nj][3] + b1;
            if (half_out) {
                __half* C = (__half*)Cout;
                *(__half2*)&C[r0 * N + c] = __floats2half2_rn(v00, v01);
                *(__half2*)&C[r1 * N + c] = __floats2half2_rn(v10, v11);
            } else {
                float* C = (float*)Cout;
                *(float2*)&C[r0 * N + c] = make_float2(v00, v01);
                *(float2*)&C[r1 * N + c] = make_float2(v10, v11);
            }
        }
    }
}

// ---------------------------------------------------------------------------
// prep: fp16 Q,K,V -> Qcat/Kcat fp16 [bh][s][128], Vt fp16 [bh][d][s]
// ---------------------------------------------------------------------------
__global__ __launch_bounds__(512)
void prep_kernel(const __half* __restrict__ Qb, const __half* __restrict__ Kb,
                 const __half* __restrict__ Vb, const float* __restrict__ J,
                 const float* __restrict__ lamp,
                 __half* __restrict__ Qc, __half* __restrict__ Kc,
                 __half* __restrict__ Vt)
{
    __shared__ float Js[4096];
    __shared__ float qn[8][64];

    int h   = blockIdx.y;
    int d   = threadIdx.x;
    int ty  = threadIdx.y;
    int tid = ty * 64 + d;

    for (int i = tid; i < 4096; i += 512) Js[i] = J[h * 4096 + i];

    int tok = blockIdx.x * 8 + ty;
    int b   = tok >> 11;
    int s   = tok & 2047;
    int bh  = (b << 4) + h;

    float q = __half2float(Qb[(size_t)tok * EMB + h * HD + d]);
    float k = __half2float(Kb[(size_t)tok * EMB + h * HD + d]);
    __half v = Vb[(size_t)tok * EMB + h * HD + d];
    qn[ty][d] = tanhf(q);
    __syncthreads();

    float accv = 0.f;
#pragma unroll 8
    for (int dd = 0; dd < 64; dd++) accv += qn[ty][dd] * Js[dd * 64 + d];

    float lam = lamp[0];
    size_t base = (size_t)bh * SEQ + s;
    Qc[base * 128 + d]      = __float2half(q * 0.125f);
    Qc[base * 128 + 64 + d] = __float2half(lam * accv);
    Kc[base * 128 + d]      = __float2half(k);
    Kc[base * 128 + 64 + d] = __float2half(tanhf(k));
    Vt[((size_t)bh * 64 + d) * SEQ + s] = v;
}

// ---------------------------------------------------------------------------
// flash16: causal attention, fp16 tensor cores, fp16 O (token-major).
// CTA: 128 q-rows, 8 warps x 16 rows, kt tiles of 64 kv.
// ---------------------------------------------------------------------------
#define FLQ_BYTES  32768
#define FLSTAGE    24576
#define FL16_SMEM  (FLQ_BYTES + 2 * FLSTAGE)

__global__ __launch_bounds__(256, 1)
void flash16_kernel(const __half* __restrict__ Qc, const __half* __restrict__ Kc,
                    const __half* __restrict__ Vt, __half* __restrict__ O)
{
    extern __shared__ __align__(1024) char smem[];
    uint32_t sbase;
    asm("{ .reg .u64 t; cvta.to.shared.u64 t, %1; cvt.u32.u64 %0, t; }"
        : "=r"(sbase) : "l"(smem));

    int tid  = threadIdx.x;
    int w    = tid >> 5;
    int lane = tid & 31;
    int lm   = lane >> 3;
    int lr   = lane & 7;
    int g    = lane >> 2;
    int tq   = lane & 3;

    int bh    = blockIdx.y;
    int b     = bh >> 4;
    int h     = bh & 15;
    int qtile = (int)gridDim.x - 1 - (int)blockIdx.x;
    int qt0   = qtile * 128;
    int nkt   = 2 * qtile + 2;

    const __half* Qg = Qc + ((size_t)bh * SEQ + qt0) * 128;
#pragma unroll
    for (int i = 0; i < 8; i++) {
        int idx = tid + i * 256;
        int r   = idx >> 4;
        int ch  = idx & 15;
        uint32_t dst = sbase + (uint32_t)(ch >> 3) * 16384
                     + (uint32_t)(r << 7) + ((uint32_t)((ch & 7) ^ (r & 7)) << 4);
        cp16s(dst, Qg + (size_t)r * 128 + ch * 8);
    }
    asm volatile("cp.async.commit_group;");

    auto issueKV = [&](int kt, int s) {
        uint32_t kb = sbase + FLQ_BYTES + (uint32_t)s * FLSTAGE;
        uint32_t vb = kb + 16384;
        const __half* Kg = Kc + ((size_t)bh * SEQ + kt * 64) * 128;
        const __half* Vg = Vt + (size_t)bh * 64 * SEQ + kt * 64;
#pragma unroll
        for (int i = 0; i < 4; i++) {
            int idx = tid + i * 256;
            int r   = idx >> 4;
            int ch  = idx & 15;
            uint32_t dst = kb + (uint32_t)(ch >> 3) * 8192
                         + (uint32_t)(r << 7) + ((uint32_t)((ch & 7) ^ (r & 7)) << 4);
            cp16s(dst, Kg + (size_t)r * 128 + ch * 8);
        }
#pragma unroll
        for (int i = 0; i < 2; i++) {
            int idx = tid + i * 256;
            int r   = idx >> 3;
            int c   = idx & 7;
            uint32_t dst = vb + (uint32_t)(r << 7) + ((uint32_t)(c ^ (r & 7)) << 4);
            cp16s(dst, Vg + (size_t)r * SEQ + c * 8);
        }
        asm volatile("cp.async.commit_group;");
    };

    issueKV(0, 0);
    issueKV(1, 1);

    asm volatile("cp.async.wait_group 2;");
    __syncthreads();

    uint32_t qf[8][4];
#pragma unroll
    for (int ks = 0; ks < 8; ks++) {
        int half = ks >> 2;
        int kc   = (ks & 3) * 2 + (lm >> 1);
        int row  = w * 16 + (lm & 1) * 8 + lr;
        uint32_t ad = sbase + (uint32_t)half * 16384
                    + (uint32_t)(row << 7) + ((uint32_t)(kc ^ (row & 7)) << 4);
        LDSM_X4(qf[ks][0], qf[ks][1], qf[ks][2], qf[ks][3], ad);
    }

    float oacc[8][4];
#pragma unroll
    for (int nt = 0; nt < 8; nt++)
#pragma unroll
        for (int t = 0; t < 4; t++) oacc[nt][t] = 0.f;
    float mrow[2] = {-1e30f, -1e30f};
    float lrow[2] = {0.f, 0.f};

    int qrow0 = qt0 + w * 16;
    int r0g   = qrow0 + g;

    for (int kt = 0; kt < nkt; kt++) {
        int s_ = kt & 1;
        if (kt + 1 < nkt) asm volatile("cp.async.wait_group 1;");
        else              asm volatile("cp.async.wait_group 0;");
        __syncthreads();

        uint32_t kb = sbase + FLQ_BYTES + (uint32_t)s_ * FLSTAGE;
        uint32_t vb = kb + 16384;

        float sacc[8][4];
#pragma unroll
        for (int nt = 0; nt < 8; nt++)
#pragma unroll
            for (int t = 0; t < 4; t++) sacc[nt][t] = 0.f;

#pragma unroll
        for (int ks = 0; ks < 8; ks++) {
            int half = ks >> 2;
            int kc   = (ks & 3) * 2 + (lm & 1);
            uint32_t kf[8][2];
#pragma unroll
            for (int nb = 0; nb < 4; nb++) {
                int row = nb * 16 + (lm >> 1) * 8 + lr;
                uint32_t ad = kb + (uint32_t)half * 8192
                            + (uint32_t)(row << 7) + ((uint32_t)(kc ^ (row & 7)) << 4);
                LDSM_X4(kf[nb * 2][0], kf[nb * 2][1],
                        kf[nb * 2 + 1][0], kf[nb * 2 + 1][1], ad);
            }
#pragma unroll
            for (int nt = 0; nt < 8; nt++)
                MMA16816H(sacc[nt], qf[ks][0], qf[ks][1], qf[ks][2], qf[ks][3],
                          kf[nt][0], kf[nt][1]);
        }

        if (kt * 64 + 63 > qrow0) {
#pragma unroll
            for (int nt = 0; nt < 8; nt++) {
                int c0 = kt * 64 + nt * 8 + 2 * tq;
                if (c0     > r0g)     sacc[nt][0] = -1e30f;
                if (c0 + 1 > r0g)     sacc[nt][1] = -1e30f;
                if (c0     > r0g + 8) sacc[nt][2] = -1e30f;
                if (c0 + 1 > r0g + 8) sacc[nt][3] = -1e30f;
            }
        }

#pragma unroll
        for (int hh = 0; hh < 2; hh++) {
            float tm = -1e30f;
#pragma unroll
            for (int nt = 0; nt < 8; nt++)
                tm = fmaxf(tm, fmaxf(sacc[nt][2 * hh], sacc[nt][2 * hh + 1]));
            tm = fmaxf(tm, __shfl_xor_sync(0xffffffffu, tm, 1));
            tm = fmaxf(tm, __shfl_xor_sync(0xffffffffu, tm, 2));
            float mnew = fmaxf(mrow[hh], tm);
            float corr = __expf(mrow[hh] - mnew);
            mrow[hh] = mnew;
            float ps = 0.f;
#pragma unroll
            for (int nt = 0; nt < 8; nt++) {
                float e0 = __expf(sacc[nt][2 * hh]     - mnew);
                float e1 = __expf(sacc[nt][2 * hh + 1] - mnew);
                sacc[nt][2 * hh]     = e0;
                sacc[nt][2 * hh + 1] = e1;
                ps += e0 + e1;
            }
            ps += __shfl_xor_sync(0xffffffffu, ps, 1);
            ps += __shfl_xor_sync(0xffffffffu, ps, 2);
            lrow[hh] = lrow[hh] * corr + ps;
#pragma unroll
            for (int nt = 0; nt < 8; nt++) {
                oacc[nt][2 * hh]     *= corr;
                oacc[nt][2 * hh + 1] *= corr;
            }
        }

        uint32_t pf[4][4];
#pragma unroll
        for (int kc16 = 0; kc16 < 4; kc16++) {
            __half2 h0 = __floats2half2_rn(sacc[2 * kc16][0],     sacc[2 * kc16][1]);
            __half2 h1 = __floats2half2_rn(sacc[2 * kc16][2],     sacc[2 * kc16][3]);
            __half2 h2 = __floats2half2_rn(sacc[2 * kc16 + 1][0], sacc[2 * kc16 + 1][1]);
            __half2 h3 = __floats2half2_rn(sacc[2 * kc16 + 1][2], sacc[2 * kc16 + 1][3]);
            pf[kc16][0] = *(uint32_t*)&h0;
            pf[kc16][1] = *(uint32_t*)&h1;
            pf[kc16][2] = *(uint32_t*)&h2;
            pf[kc16][3] = *(uint32_t*)&h3;
        }

#pragma unroll
        for (int kc16 = 0; kc16 < 4; kc16++) {
            int kc = kc16 * 2 + (lm & 1);
            uint32_t vf[8][2];
#pragma unroll
            for (int nb = 0; nb < 4; nb++) {
                int row = nb * 16 + (lm >> 1) * 8 + lr;
                uint32_t ad = vb + (uint32_t)(row << 7)
                            + ((uint32_t)(kc ^ (row & 7)) << 4);
                LDSM_X4(vf[nb * 2][0], vf[nb * 2][1],
                        vf[nb * 2 + 1][0], vf[nb * 2 + 1][1], ad);
            }
#pragma unroll
            for (int nt = 0; nt < 8; nt++)
                MMA16816H(oacc[nt], pf[kc16][0], pf[kc16][1], pf[kc16][2], pf[kc16][3],
                          vf[nt][0], vf[nt][1]);
        }

        __syncthreads();
        if (kt + 2 < nkt) issueKV(kt + 2, s_);
    }

    // epilogue: fp16 O token-major
    float inv0 = 1.0f / lrow[0];
    float inv1 = 1.0f / lrow[1];
    size_t rt0 = (size_t)(b * SEQ + qt0 + w * 16 + g);
    __half* O0 = O + rt0 * EMB + h * 64;
    __half* O1 = O0 + (size_t)8 * EMB;
#pragma unroll
    for (int nt = 0; nt < 8; nt++) {
        int c = nt * 8 + 2 * tq;
        *(__half2*)&O0[c] = __floats2half2_rn(oacc[nt][0] * inv0, oacc[nt][1] * inv0);
        *(__half2*)&O1[c] = __floats2half2_rn(oacc[nt][2] * inv1, oacc[nt][3] * inv1);
    }
}

// ---------------------------------------------------------------------------
// launch
// ---------------------------------------------------------------------------
extern "C" void kernel_launch(void* const* d_in, const int* in_sizes, int n_in,
                              void* d_out, int out_size)
{
    const float* x   = (const float*)d_in[0];
    const float* Wq  = (const float*)d_in[1];
    const float* bq  = (const float*)d_in[2];
    const float* Wk  = (const float*)d_in[3];
    const float* bk  = (const float*)d_in[4];
    const float* Wv  = (const float*)d_in[5];
    const float* bv  = (const float*)d_in[6];
    const float* Wo  = (const float*)d_in[7];
    const float* bo  = (const float*)d_in[8];
    const float* J   = (const float*)d_in[9];
    const float* lam = (const float*)d_in[10];
    float* out = (float*)d_out;

    void* p = nullptr;
    cudaGetSymbolAddress(&p, g_hscratch);
    __half* hs  = (__half*)p;
    __half* x16 = hs + HX;
    __half* w16 = hs + HW;
    __half* q16 = hs + HQ;
    __half* k16 = hs + HK;
    __half* v16 = hs + HV;
    __half* qc  = hs + HQC;
    __half* kc  = hs + HKC;
    __half* vt  = hs + HVT;
    __half* o16 = hs + HO;

    const int WSZ = EMB * EMB;
    __half* wq16 = w16 + 0 * WSZ;
    __half* wk16 = w16 + 1 * WSZ;
    __half* wv16 = w16 + 2 * WSZ;
    __half* wo16 = w16 + 3 * WSZ;

    // conversions
    convert_kernel<<<(N_TOK * EMB / 4 + 255) / 256, 256>>>(x, x16, N_TOK * EMB / 4);
    dim3 tg(32, 32), tb(256);
    transpose_convert_kernel<<<tg, tb>>>(Wq, wq16);
    transpose_convert_kernel<<<tg, tb>>>(Wk, wk16);
    transpose_convert_kernel<<<tg, tb>>>(Wv, wv16);
    transpose_convert_kernel<<<tg, tb>>>(Wo, wo16);

    cudaFuncSetAttribute(gemm_fp16, cudaFuncAttributeMaxDynamicSharedMemorySize, GSMEM);
    dim3 gg(8, 32), gb(256);
    gemm_fp16<<<gg, gb, GSMEM>>>(x16, wq16, bq, q16, 1);
    gemm_fp16<<<gg, gb, GSMEM>>>(x16, wk16, bk, k16, 1);
    gemm_fp16<<<gg, gb, GSMEM>>>(x16, wv16, bv, v16, 1);

    dim3 prep_grid(N_TOK / 8, HEADS), prep_blk(64, 8);
    prep_kernel<<<prep_grid, prep_blk>>>(q16, k16, v16, J, lam, qc, kc, vt);

    cudaFuncSetAttribute(flash16_kernel, cudaFuncAttributeMaxDynamicSharedMemorySize,
                         FL16_SMEM);
    dim3 fl_grid(SEQ / 128, BH);
    flash16_kernel<<<fl_grid, 256, FL16_SMEM>>>(qc, kc, vt, o16);

    gemm_fp16<<<gg, gb, GSMEM>>>(o16, wo16, bo, out, 0);
}

// round 10
// speedup vs baseline: 6.9148x; 1.0058x over previous
#include <cuda_runtime.h>
#include <cuda_fp16.h>
#include <math.h>
#include <stdint.h>

// ---------------------------------------------------------------------------
// QBNN attention, all-fp16 tensor-core pipeline. B=2, S=2048, E=1024, H=16, hd=64.
//  0) convert: x -> fp16 ; W* -> transposed fp16 (fused 4-way)
//  1) gemm_fp16: Q,K,V = x@W + b  (single-pass fp16 mma, fp16 out)
//  2) prep: Qcat(log2e-scaled)/Kcat fp16 [bh][s][128], Vt fp16 [bh][d][s]
//  3) flash16: causal attention, fp16 mma, log2-domain softmax (ex2.f16x2)
//  4) gemm_fp16: out = O@Wo + bo (fp32 out)
// ---------------------------------------------------------------------------

#define N_TOK   4096
#define EMB     1024
#define HEADS   16
#define HD      64
#define SEQ     2048
#define BH      32
#define LOG2E   1.4426950408889634f

// fp16 scratch arena
#define HX    0
#define HW    (HX   + N_TOK*EMB)
#define HQ    (HW   + 4*EMB*EMB)
#define HK    (HQ   + N_TOK*EMB)
#define HV    (HK   + N_TOK*EMB)
#define HQC   (HV   + N_TOK*EMB)
#define HKC   (HQC  + BH*SEQ*128)
#define HVT   (HKC  + BH*SEQ*128)
#define HO    (HVT  + BH*64*SEQ)
#define HTOTAL (HO  + N_TOK*EMB)
__device__ __half g_hscratch[HTOTAL];

// ---------------------------------------------------------------------------
// convert: fp32 -> fp16 elementwise
// ---------------------------------------------------------------------------
__global__ __launch_bounds__(256)
void convert_kernel(const float* __restrict__ src, __half* __restrict__ dst, int n4)
{
    int i = blockIdx.x * blockDim.x + threadIdx.x;
    if (i >= n4) return;
    float4 v = ((const float4*)src)[i];
    __half2 h0 = __floats2half2_rn(v.x, v.y);
    __half2 h1 = __floats2half2_rn(v.z, v.w);
    uint2 w;
    w.x = *(uint32_t*)&h0;
    w.y = *(uint32_t*)&h1;
    ((uint2*)dst)[i] = w;
}

// ---------------------------------------------------------------------------
// fused transpose+convert of all 4 weights: W[k][n] fp32 -> Wt[n][k] fp16
// blockIdx.z selects the weight matrix.
// ---------------------------------------------------------------------------
__global__ __launch_bounds__(256)
void transpose4_kernel(const float* __restrict__ W0, const float* __restrict__ W1,
                       const float* __restrict__ W2, const float* __restrict__ W3,
                       __half* __restrict__ Tbase)
{
    __shared__ float tile[32][33];
    int z  = blockIdx.z;
    const float* W = (z == 0) ? W0 : (z == 1) ? W1 : (z == 2) ? W2 : W3;
    __half* T = Tbase + (size_t)z * EMB * EMB;

    int k0 = blockIdx.y * 32;
    int n0 = blockIdx.x * 32;
    int tx = threadIdx.x & 31;
    int ty = threadIdx.x >> 5;
#pragma unroll
    for (int j = 0; j < 4; j++)
        tile[ty + j * 8][tx] = W[(size_t)(k0 + ty + j * 8) * EMB + n0 + tx];
    __syncthreads();
#pragma unroll
    for (int j = 0; j < 4; j++) {
        int n = ty + j * 8;
        T[(size_t)(n0 + n) * EMB + k0 + tx] = __float2half(tile[tx][n]);
    }
}

// ---------------------------------------------------------------------------
// helpers
// ---------------------------------------------------------------------------
#define MMA16816H(d, a0, a1, a2, a3, b0, b1)                                 \
    asm volatile(                                                            \
        "mma.sync.aligned.m16n8k16.row.col.f32.f16.f16.f32 "                 \
        "{%0,%1,%2,%3}, {%4,%5,%6,%7}, {%8,%9}, {%0,%1,%2,%3};"              \
        : "+f"(d[0]), "+f"(d[1]), "+f"(d[2]), "+f"(d[3])                     \
        : "r"(a0), "r"(a1), "r"(a2), "r"(a3), "r"(b0), "r"(b1))

#define LDSM_X4(r0, r1, r2, r3, addr)                                        \
    asm volatile("ldmatrix.sync.aligned.m8n8.x4.shared.b16 {%0,%1,%2,%3}, [%4];" \
        : "=r"(r0), "=r"(r1), "=r"(r2), "=r"(r3) : "r"(addr))

__device__ __forceinline__ void cp16s(uint32_t smem_dst, const void* gmem_src)
{
    asm volatile("cp.async.cg.shared.global [%0], [%1], 16;"
                 :: "r"(smem_dst), "l"(gmem_src));
}

__device__ __forceinline__ uint32_t h2exp2(uint32_t x)
{
    uint32_t r;
    asm("ex2.approx.f16x2 %0, %1;" : "=r"(r) : "r"(x));
    return r;
}

__device__ __forceinline__ float tanh_fast(float x)
{
    float r;
    asm("tanh.approx.f32 %0, %1;" : "=f"(r) : "f"(x));
    return r;
}

// ---------------------------------------------------------------------------
// Single-pass fp16 tensor-core GEMM (R8-proven).
// ---------------------------------------------------------------------------
#define GSTAGE  32768
#define GSMEM   (3 * GSTAGE)

__global__ __launch_bounds__(256, 2)
void gemm_fp16(const __half* __restrict__ A, const __half* __restrict__ Bt,
               const float* __restrict__ bias, void* __restrict__ Cout, int half_out)
{
    extern __shared__ __align__(1024) char smem[];
    const int K = 1024, N = 1024;
    uint32_t sbase;
    asm("{ .reg .u64 t; cvta.to.shared.u64 t, %1; cvt.u32.u64 %0, t; }"
        : "=r"(sbase) : "l"(smem));

    int tid  = threadIdx.x;
    int warp = tid >> 5;
    int lane = tid & 31;
    int wm   = warp & 1;
    int wn   = warp >> 1;
    int m0   = blockIdx.y * 128;
    int n0   = blockIdx.x * 128;

    float acc[4][4][4];
#pragma unroll
    for (int mi = 0; mi < 4; mi++)
#pragma unroll
        for (int nj = 0; nj < 4; nj++)
#pragma unroll
            for (int t = 0; t < 4; t++) acc[mi][nj][t] = 0.f;

    auto issue = [&](int chunk, int stg) {
        int k0 = chunk << 6;
        const __half* Ap = A  + (size_t)m0 * K + k0;
        const __half* Bp = Bt + (size_t)n0 * K + k0;
        uint32_t aBuf = sbase + stg * GSTAGE;
        uint32_t bBuf = aBuf + 16384;
#pragma unroll
        for (int i = 0; i < 4; i++) {
            int idx = tid + i * 256;
            int r   = idx >> 3;
            int c   = idx & 7;
            uint32_t sw = (uint32_t)(r << 7) | ((uint32_t)(c ^ (r & 7)) << 4);
            cp16s(aBuf + sw, Ap + (size_t)r * K + c * 8);
            cp16s(bBuf + sw, Bp + (size_t)r * K + c * 8);
        }
        asm volatile("cp.async.commit_group;");
    };

    issue(0, 0);
    issue(1, 1);

    int lm  = lane >> 3;
    int lr  = lane & 7;

    for (int t = 0; t < 16; t++) {
        int stg = t % 3;
        if (t < 15) asm volatile("cp.async.wait_group 1;");
        else        asm volatile("cp.async.wait_group 0;");
        __syncthreads();

        uint32_t aBuf = sbase + stg * GSTAGE;
        uint32_t bBuf = aBuf + 16384;

#pragma unroll
        for (int kk = 0; kk < 64; kk += 16) {
            int kc = kk >> 3;
            uint32_t af[4][4];
#pragma unroll
            for (int mi = 0; mi < 4; mi++) {
                int row = wm * 64 + mi * 16 + (lm & 1) * 8 + lr;
                int ch  = kc + (lm >> 1);
                uint32_t ad = aBuf + (uint32_t)(row << 7) + ((uint32_t)(ch ^ (row & 7)) << 4);
                LDSM_X4(af[mi][0], af[mi][1], af[mi][2], af[mi][3], ad);
            }
            uint32_t bf_[4][2];
#pragma unroll
            for (int njp = 0; njp < 2; njp++) {
                int row = wn * 32 + njp * 16 + (lm >> 1) * 8 + lr;
                int ch  = kc + (lm & 1);
                uint32_t bd = bBuf + (uint32_t)(row << 7) + ((uint32_t)(ch ^ (row & 7)) << 4);
                LDSM_X4(bf_[njp * 2][0], bf_[njp * 2][1],
                        bf_[njp * 2 + 1][0], bf_[njp * 2 + 1][1], bd);
            }
#pragma unroll
            for (int mi = 0; mi < 4; mi++)
#pragma unroll
                for (int nj = 0; nj < 4; nj++)
                    MMA16816H(acc[mi][nj], af[mi][0], af[mi][1], af[mi][2], af[mi][3],
                              bf_[nj][0], bf_[nj][1]);
        }

        if (t + 2 < 16) issue(t + 2, (t + 2) % 3);
    }

    int g  = lane >> 2;
    int tq = lane & 3;
#pragma unroll
    for (int mi = 0; mi < 4; mi++) {
        size_t r0 = (size_t)(m0 + wm * 64 + mi * 16 + g);
        size_t r1 = r0 + 8;
#pragma unroll
        for (int nj = 0; nj < 4; nj++) {
            int c = n0 + wn * 32 + nj * 8 + tq * 2;
            float b0 = bias[c], b1 = bias[c + 1];
            float v00 = acc[mi][nj][0] + b0, v01 = acc[mi][nj][1] + b1;
            float v10 = acc[mi][nj][2] + b0, v11 = acc[mi][nj][3] + b1;
            if (half_out) {
                __half* C = (__half*)Cout;
                *(__half2*)&C[r0 * N + c] = __floats2half2_rn(v00, v01);
                *(__half2*)&C[r1 * N + c] = __floats2half2_rn(v10, v11);
            } else {
                float* C = (float*)Cout;
                *(float2*)&C[r0 * N + c] = make_float2(v00, v01);
                *(float2*)&C[r1 * N + c] = make_float2(v10, v11);
            }
        }
    }
}

// ---------------------------------------------------------------------------
// prep: Qcat scaled by LOG2E (log2-domain scores), Kcat, Vt.
// ---------------------------------------------------------------------------
__global__ __launch_bounds__(512)
void prep_kernel(const __half* __restrict__ Qb, const __half* __restrict__ Kb,
                 const __half* __restrict__ Vb, const float* __restrict__ J,
                 const float* __restrict__ lamp,
                 __half* __restrict__ Qc, __half* __restrict__ Kc,
                 __half* __restrict__ Vt)
{
    __shared__ float Js[4096];
    __shared__ float qn[8][64];

    int h   = blockIdx.y;
    int d   = threadIdx.x;
    int ty  = threadIdx.y;
    int tid = ty * 64 + d;

    for (int i = tid; i < 4096; i += 512) Js[i] = J[h * 4096 + i];

    int tok = blockIdx.x * 8 + ty;
    int b   = tok >> 11;
    int s   = tok & 2047;
    int bh  = (b << 4) + h;

    float q = __half2float(Qb[(size_t)tok * EMB + h * HD + d]);
    float k = __half2float(Kb[(size_t)tok * EMB + h * HD + d]);
    __half v = Vb[(size_t)tok * EMB + h * HD + d];
    qn[ty][d] = tanh_fast(q);
    __syncthreads();

    float accv = 0.f;
#pragma unroll 8
    for (int dd = 0; dd < 64; dd++) accv += qn[ty][dd] * Js[dd * 64 + d];

    float lam = lamp[0];
    size_t base = (size_t)bh * SEQ + s;
    Qc[base * 128 + d]      = __float2half(q * 0.125f * LOG2E);
    Qc[base * 128 + 64 + d] = __float2half(lam * accv * LOG2E);
    Kc[base * 128 + d]      = __float2half(k);
    Kc[base * 128 + 64 + d] = __float2half(tanh_fast(k));
    Vt[((size_t)bh * 64 + d) * SEQ + s] = v;
}

// ---------------------------------------------------------------------------
// flash16: causal attention, fp16 mma, log2-domain softmax via ex2.f16x2.
// CTA 128 q-rows, 8 warps; kt tiles of 64 kv; 3-stage KV cp.async, 1 sync/tile.
// ---------------------------------------------------------------------------
#define FLQ_BYTES  32768
#define FLSTAGE    24576
#define FL16_SMEM  (FLQ_BYTES + 3 * FLSTAGE)

__global__ __launch_bounds__(256, 1)
void flash16_kernel(const __half* __restrict__ Qc, const __half* __restrict__ Kc,
                    const __half* __restrict__ Vt, __half* __restrict__ O)
{
    extern __shared__ __align__(1024) char smem[];
    uint32_t sbase;
    asm("{ .reg .u64 t; cvta.to.shared.u64 t, %1; cvt.u32.u64 %0, t; }"
        : "=r"(sbase) : "l"(smem));

    int tid  = threadIdx.x;
    int w    = tid >> 5;
    int lane = tid & 31;
    int lm   = lane >> 3;
    int lr   = lane & 7;
    int g    = lane >> 2;
    int tq   = lane & 3;

    int bh    = blockIdx.y;
    int b     = bh >> 4;
    int h     = bh & 15;
    int qtile = (int)gridDim.x - 1 - (int)blockIdx.x;
    int qt0   = qtile * 128;
    int nkt   = 2 * qtile + 2;

    const __half* Qg = Qc + ((size_t)bh * SEQ + qt0) * 128;
#pragma unroll
    for (int i = 0; i < 8; i++) {
        int idx = tid + i * 256;
        int r   = idx >> 4;
        int ch  = idx & 15;
        uint32_t dst = sbase + (uint32_t)(ch >> 3) * 16384
                     + (uint32_t)(r << 7) + ((uint32_t)((ch & 7) ^ (r & 7)) << 4);
        cp16s(dst, Qg + (size_t)r * 128 + ch * 8);
    }
    asm volatile("cp.async.commit_group;");

    auto issueKV = [&](int kt, int s) {
        uint32_t kb = sbase + FLQ_BYTES + (uint32_t)s * FLSTAGE;
        uint32_t vb = kb + 16384;
        const __half* Kg = Kc + ((size_t)bh * SEQ + kt * 64) * 128;
        const __half* Vg = Vt + (size_t)bh * 64 * SEQ + kt * 64;
#pragma unroll
        for (int i = 0; i < 4; i++) {
            int idx = tid + i * 256;
            int r   = idx >> 4;
            int ch  = idx & 15;
            uint32_t dst = kb + (uint32_t)(ch >> 3) * 8192
                         + (uint32_t)(r << 7) + ((uint32_t)((ch & 7) ^ (r & 7)) << 4);
            cp16s(dst, Kg + (size_t)r * 128 + ch * 8);
        }
#pragma unroll
        for (int i = 0; i < 2; i++) {
            int idx = tid + i * 256;
            int r   = idx >> 3;
            int c   = idx & 7;
            uint32_t dst = vb + (uint32_t)(r << 7) + ((uint32_t)(c ^ (r & 7)) << 4);
            cp16s(dst, Vg + (size_t)r * SEQ + c * 8);
        }
        asm volatile("cp.async.commit_group;");
    };

    issueKV(0, 0);
    issueKV(1, 1);

    asm volatile("cp.async.wait_group 2;");
    __syncthreads();

    uint32_t qf[8][4];
#pragma unroll
    for (int ks = 0; ks < 8; ks++) {
        int half = ks >> 2;
        int kc   = (ks & 3) * 2 + (lm >> 1);
        int row  = w * 16 + (lm & 1) * 8 + lr;
        uint32_t ad = sbase + (uint32_t)half * 16384
                    + (uint32_t)(row << 7) + ((uint32_t)(kc ^ (row & 7)) << 4);
        LDSM_X4(qf[ks][0], qf[ks][1], qf[ks][2], qf[ks][3], ad);
    }

    float oacc[8][4];
#pragma unroll
    for (int nt = 0; nt < 8; nt++)
#pragma unroll
        for (int t = 0; t < 4; t++) oacc[nt][t] = 0.f;
    float mrow[2] = {-1e30f, -1e30f};
    float lrow[2] = {0.f, 0.f};

    int qrow0 = qt0 + w * 16;
    int r0g   = qrow0 + g;

    for (int kt = 0; kt < nkt; kt++) {
        int s_ = kt % 3;
        if (kt + 1 < nkt) asm volatile("cp.async.wait_group 1;");
        else              asm volatile("cp.async.wait_group 0;");
        __syncthreads();

        // 3-stage: safe to refill stage (kt+2)%3 right after the sync —
        // its previous readers were iteration kt-1, already past this barrier.
        if (kt + 2 < nkt) issueKV(kt + 2, (kt + 2) % 3);

        uint32_t kb = sbase + FLQ_BYTES + (uint32_t)s_ * FLSTAGE;
        uint32_t vb = kb + 16384;

        float sacc[8][4];
#pragma unroll
        for (int nt = 0; nt < 8; nt++)
#pragma unroll
            for (int t = 0; t < 4; t++) sacc[nt][t] = 0.f;

#pragma unroll
        for (int ks = 0; ks < 8; ks++) {
            int half = ks >> 2;
            int kc   = (ks & 3) * 2 + (lm & 1);
            uint32_t kf[8][2];
#pragma unroll
            for (int nb = 0; nb < 4; nb++) {
                int row = nb * 16 + (lm >> 1) * 8 + lr;
                uint32_t ad = kb + (uint32_t)half * 8192
                            + (uint32_t)(row << 7) + ((uint32_t)(kc ^ (row & 7)) << 4);
                LDSM_X4(kf[nb * 2][0], kf[nb * 2][1],
                        kf[nb * 2 + 1][0], kf[nb * 2 + 1][1], ad);
            }
#pragma unroll
            for (int nt = 0; nt < 8; nt++)
                MMA16816H(sacc[nt], qf[ks][0], qf[ks][1], qf[ks][2], qf[ks][3],
                          kf[nt][0], kf[nt][1]);
        }

        if (kt * 64 + 63 > qrow0) {
#pragma unroll
            for (int nt = 0; nt < 8; nt++) {
                int c0 = kt * 64 + nt * 8 + 2 * tq;
                if (c0     > r0g)     sacc[nt][0] = -1e30f;
                if (c0 + 1 > r0g)     sacc[nt][1] = -1e30f;
                if (c0     > r0g + 8) sacc[nt][2] = -1e30f;
                if (c0 + 1 > r0g + 8) sacc[nt][3] = -1e30f;
            }
        }

        // ---- log2-domain online softmax ----
        float tm0 = -1e30f, tm1 = -1e30f;
#pragma unroll
        for (int nt = 0; nt < 8; nt++) {
            tm0 = fmaxf(tm0, fmaxf(sacc[nt][0], sacc[nt][1]));
            tm1 = fmaxf(tm1, fmaxf(sacc[nt][2], sacc[nt][3]));
        }
        tm0 = fmaxf(tm0, __shfl_xor_sync(0xffffffffu, tm0, 1));
        tm0 = fmaxf(tm0, __shfl_xor_sync(0xffffffffu, tm0, 2));
        tm1 = fmaxf(tm1, __shfl_xor_sync(0xffffffffu, tm1, 1));
        tm1 = fmaxf(tm1, __shfl_xor_sync(0xffffffffu, tm1, 2));

        float mnew0 = fmaxf(mrow[0], tm0);
        float mnew1 = fmaxf(mrow[1], tm1);
        float corr0 = exp2f(mrow[0] - mnew0);
        float corr1 = exp2f(mrow[1] - mnew1);
        mrow[0] = mnew0;
        mrow[1] = mnew1;
#pragma unroll
        for (int nt = 0; nt < 8; nt++) {
            oacc[nt][0] *= corr0; oacc[nt][1] *= corr0;
            oacc[nt][2] *= corr1; oacc[nt][3] *= corr1;
        }

        // exp2 in fp16x2: produces the P fragments directly
        uint32_t pf[4][4];
        float ps0 = 0.f, ps1 = 0.f;
#pragma unroll
        for (int nt = 0; nt < 8; nt++) {
            __half2 d0 = __floats2half2_rn(sacc[nt][0] - mnew0, sacc[nt][1] - mnew0);
            __half2 d1 = __floats2half2_rn(sacc[nt][2] - mnew1, sacc[nt][3] - mnew1);
            uint32_t p0 = h2exp2(*(uint32_t*)&d0);
            uint32_t p1 = h2exp2(*(uint32_t*)&d1);
            float2 f0 = __half22float2(*(__half2*)&p0);
            float2 f1 = __half22float2(*(__half2*)&p1);
            ps0 += f0.x + f0.y;
            ps1 += f1.x + f1.y;
            pf[nt >> 1][(nt & 1) * 2]     = p0;
            pf[nt >> 1][(nt & 1) * 2 + 1] = p1;
        }
        ps0 += __shfl_xor_sync(0xffffffffu, ps0, 1);
        ps0 += __shfl_xor_sync(0xffffffffu, ps0, 2);
        ps1 += __shfl_xor_sync(0xffffffffu, ps1, 1);
        ps1 += __shfl_xor_sync(0xffffffffu, ps1, 2);
        lrow[0] = lrow[0] * corr0 + ps0;
        lrow[1] = lrow[1] * corr1 + ps1;

        // O += P @ V
#pragma unroll
        for (int kc16 = 0; kc16 < 4; kc16++) {
            int kc = kc16 * 2 + (lm & 1);
            uint32_t vf[8][2];
#pragma unroll
            for (int nb = 0; nb < 4; nb++) {
                int row = nb * 16 + (lm >> 1) * 8 + lr;
                uint32_t ad = vb + (uint32_t)(row << 7)
                            + ((uint32_t)(kc ^ (row & 7)) << 4);
                LDSM_X4(vf[nb * 2][0], vf[nb * 2][1],
                        vf[nb * 2 + 1][0], vf[nb * 2 + 1][1], ad);
            }
#pragma unroll
            for (int nt = 0; nt < 8; nt++)
                MMA16816H(oacc[nt], pf[kc16][0], pf[kc16][1], pf[kc16][2], pf[kc16][3],
                          vf[nt][0], vf[nt][1]);
        }
    }

    // epilogue: fp16 O token-major
    float inv0 = 1.0f / lrow[0];
    float inv1 = 1.0f / lrow[1];
    size_t rt0 = (size_t)(b * SEQ + qt0 + w * 16 + g);
    __half* O0 = O + rt0 * EMB + h * 64;
    __half* O1 = O0 + (size_t)8 * EMB;
#pragma unroll
    for (int nt = 0; nt < 8; nt++) {
        int c = nt * 8 + 2 * tq;
        *(__half2*)&O0[c] = __floats2half2_rn(oacc[nt][0] * inv0, oacc[nt][1] * inv0);
        *(__half2*)&O1[c] = __floats2half2_rn(oacc[nt][2] * inv1, oacc[nt][3] * inv1);
    }
}

// ---------------------------------------------------------------------------
// launch
// ---------------------------------------------------------------------------
extern "C" void kernel_launch(void* const* d_in, const int* in_sizes, int n_in,
                              void* d_out, int out_size)
{
    const float* x   = (const float*)d_in[0];
    const float* Wq  = (const float*)d_in[1];
    const float* bq  = (const float*)d_in[2];
    const float* Wk  = (const float*)d_in[3];
    const float* bk  = (const float*)d_in[4];
    const float* Wv  = (const float*)d_in[5];
    const float* bv  = (const float*)d_in[6];
    const float* Wo  = (const float*)d_in[7];
    const float* bo  = (const float*)d_in[8];
    const float* J   = (const float*)d_in[9];
    const float* lam = (const float*)d_in[10];
    float* out = (float*)d_out;

    void* p = nullptr;
    cudaGetSymbolAddress(&p, g_hscratch);
    __half* hs  = (__half*)p;
    __half* x16 = hs + HX;
    __half* w16 = hs + HW;
    __half* q16 = hs + HQ;
    __half* k16 = hs + HK;
    __half* v16 = hs + HV;
    __half* qc  = hs + HQC;
    __half* kc  = hs + HKC;
    __half* vt  = hs + HVT;
    __half* o16 = hs + HO;

    const int WSZ = EMB * EMB;
    __half* wq16 = w16 + 0 * WSZ;
    __half* wk16 = w16 + 1 * WSZ;
    __half* wv16 = w16 + 2 * WSZ;
    __half* wo16 = w16 + 3 * WSZ;

    convert_kernel<<<(N_TOK * EMB / 4 + 255) / 256, 256>>>(x, x16, N_TOK * EMB / 4);
    dim3 tg(32, 32, 4), tb(256);
    transpose4_kernel<<<tg, tb>>>(Wq, Wk, Wv, Wo, w16);

    cudaFuncSetAttribute(gemm_fp16, cudaFuncAttributeMaxDynamicSharedMemorySize, GSMEM);
    dim3 gg(8, 32), gb(256);
    gemm_fp16<<<gg, gb, GSMEM>>>(x16, wq16, bq, q16, 1);
    gemm_fp16<<<gg, gb, GSMEM>>>(x16, wk16, bk, k16, 1);
    gemm_fp16<<<gg, gb, GSMEM>>>(x16, wv16, bv, v16, 1);

    dim3 prep_grid(N_TOK / 8, HEADS), prep_blk(64, 8);
    prep_kernel<<<prep_grid, prep_blk>>>(q16, k16, v16, J, lam, qc, kc, vt);

    cudaFuncSetAttribute(flash16_kernel, cudaFuncAttributeMaxDynamicSharedMemorySize,
                         FL16_SMEM);
    dim3 fl_grid(SEQ / 128, BH);
    flash16_kernel<<<fl_grid, 256, FL16_SMEM>>>(qc, kc, vt, o16);

    gemm_fp16<<<gg, gb, GSMEM>>>(o16, wo16, bo, out, 0);
}